// round 9
// baseline (speedup 1.0000x reference)
#include <cuda_runtime.h>
#include <cuda_bf16.h>
#include <stdint.h>

// Problem constants (match reference setup_inputs)
#define TOTAL   262144        // B*N = 16*16384
#define NGROUP  1024          // NUM_GROUPS
#define GSENT   1024          // sentinel group for masked-out nodes
#define NBLK    512           // number of stable-sort chunks
#define CHUNK   512           // TOTAL / NBLK
#define RANK_WARPS 4          // warps (=chunks) per rank block
#define LOSS_THREADS 256
#define LOSS_BLOCKS  1024     // 8192 warps
#define CHUNK_T      32       // sorted positions per warp
#define CSCAN_BLOCKS ((NGROUP + 1 + 7) / 8)   // 129 blocks of 8 warps

// ---------------- scratch (static __device__, no allocation) ----------------
__device__ int   d_rg[TOTAL];                    // packed (g<<16)|rank
__device__ int   d_histT[(NGROUP + 1) * NBLK];   // [g][b]
__device__ int   d_offT [(NGROUP + 1) * NBLK];   // [g][b] exclusive over b
__device__ int   d_counts[NGROUP + 1];
__device__ int   d_starts[NGROUP + 2];
__device__ int2  d_osg[TOTAL];                   // (orig index, group) per sorted pos
__device__ float d_partials[2 * LOSS_BLOCKS];
__device__ int   d_done;      // zero-init; last loss block resets to 0
__device__ int   d_csDone;    // zero-init; last colscan block resets to 0

// ---------------- threefry2x32 (JAX partitionable mode) ----------------
__device__ __forceinline__ unsigned rotl32(unsigned v, int d) {
    return (v << d) | (v >> (32 - d));
}

__device__ __forceinline__ void threefry2x32(unsigned k0, unsigned k1,
                                             unsigned& x0, unsigned& x1) {
    const unsigned ks0 = k0, ks1 = k1, ks2 = k0 ^ k1 ^ 0x1BD11BDAu;
    x0 += ks0; x1 += ks1;
#define TF_R4(a,b,c,d)                                  \
    x0 += x1; x1 = rotl32(x1, a); x1 ^= x0;             \
    x0 += x1; x1 = rotl32(x1, b); x1 ^= x0;             \
    x0 += x1; x1 = rotl32(x1, c); x1 ^= x0;             \
    x0 += x1; x1 = rotl32(x1, d); x1 ^= x0;
    TF_R4(13,15,26, 6); x0 += ks1; x1 += ks2 + 1u;
    TF_R4(17,29,16,24); x0 += ks2; x1 += ks0 + 2u;
    TF_R4(13,15,26, 6); x0 += ks0; x1 += ks1 + 3u;
    TF_R4(17,29,16,24); x0 += ks1; x1 += ks2 + 4u;
    TF_R4(13,15,26, 6); x0 += ks2; x1 += ks0 + 5u;
#undef TF_R4
}

// u[t]: counter = 64-bit flat index -> (hi=0, lo=t); draw = fold(out0^out1).
__device__ __forceinline__ float jax_uniform_at(int t) {
    unsigned x0 = 0u;
    unsigned x1 = (unsigned)t;
    threefry2x32(0u, 42u, x0, x1);       // jax.random.key(42) -> (0, 42)
    const unsigned bits = x0 ^ x1;
    return __uint_as_float((bits >> 9) | 0x3f800000u) - 1.0f;
}

// negative sorted-position for sorted index t
__device__ __forceinline__ int neg_pos(int t, int st, int cnt, int valid_total) {
    const float u = jax_uniform_at(t);
    const int comp = max(valid_total - cnt, 1);
    int r = (int)(u * (float)comp);
    if (r > comp - 1) r = comp - 1;
    int np_ = (r < st) ? r : r + cnt;
    if (np_ < 0) np_ = 0;
    if (np_ > TOTAL - 1) np_ = TOTAL - 1;
    return np_;
}

// ---------------- K1: stable per-chunk rank + per-chunk histogram ----------------
// One warp per 512-element chunk; 4-round software prefetch for MLP.
__global__ void __launch_bounds__(RANK_WARPS * 32)
rank_kernel(const int* __restrict__ groups, const int* __restrict__ mask) {
    __shared__ int bins[RANK_WARPS][NGROUP + 1];
    const int warpId = threadIdx.x >> 5;
    const int lane = threadIdx.x & 31;
    const int b = blockIdx.x * RANK_WARPS + warpId;       // chunk id 0..511
    int* myb = bins[warpId];
    for (int i = lane; i <= NGROUP; i += 32) myb[i] = 0;
    __syncwarp();
    const int base = b * CHUNK;
    #pragma unroll 1
    for (int j = 0; j < CHUNK; j += 128) {                // 4 rounds per batch
        int gv[4];
        #pragma unroll
        for (int k = 0; k < 4; k++) {                     // batched loads (MLP 8)
            const int i = base + j + k * 32 + lane;
            const int mv = __ldg(mask + i);
            const int gr = __ldg(groups + i);
            gv[k] = mv ? gr : GSENT;
        }
        #pragma unroll
        for (int k = 0; k < 4; k++) {                     // stable order kept
            const int i = base + j + k * 32 + lane;
            const int g = gv[k];
            const unsigned m = __match_any_sync(0xffffffffu, g);
            const int rankInWarp = __popc(m & ((1u << lane) - 1u));
            const int leader = __ffs(m) - 1;
            int baseBin = 0;
            if (lane == leader) baseBin = atomicAdd(&myb[g], __popc(m));
            baseBin = __shfl_sync(0xffffffffu, baseBin, leader);
            d_rg[i] = (g << 16) | (baseBin + rankInWarp);
            __syncwarp();
        }
    }
    for (int i = lane; i <= NGROUP; i += 32) d_histT[i * NBLK + b] = myb[i];
}

// ---------------- K2: per-group scan over chunks + fused starts scan ------------
__global__ void __launch_bounds__(256)
colscan_kernel() {
    const int warpId = threadIdx.x >> 5;
    const int lane = threadIdx.x & 31;
    const int g = blockIdx.x * 8 + warpId;
    if (g <= NGROUP) {
        const int baseIdx = g * NBLK;
        int cum = 0;
        #pragma unroll
        for (int b0 = 0; b0 < NBLK; b0 += 32) {
            const int h = d_histT[baseIdx + b0 + lane];     // coalesced 128B
            int x = h;
            #pragma unroll
            for (int o = 1; o < 32; o <<= 1) {
                const int y = __shfl_up_sync(0xffffffffu, x, o);
                if (lane >= o) x += y;
            }
            d_offT[baseIdx + b0 + lane] = cum + x - h;      // exclusive
            cum += __shfl_sync(0xffffffffu, x, 31);
        }
        if (lane == 0) d_counts[g] = cum;
    }
    // ---- fused starts: last finishing block's warp 0 scans counts ----
    __shared__ int isLast;
    __syncthreads();
    if (threadIdx.x == 0) {
        __threadfence();
        isLast = (atomicAdd(&d_csDone, 1) == CSCAN_BLOCKS - 1);
    }
    __syncthreads();
    if (isLast && warpId == 0) {
        int cum = 0;
        #pragma unroll 1
        for (int b0 = 0; b0 <= NGROUP; b0 += 32) {
            const int idx = b0 + lane;
            // volatile: other SMs wrote counts; bypass potentially-stale L1
            const int v = (idx <= NGROUP) ? *(volatile int*)(d_counts + idx) : 0;
            int x = v;
            #pragma unroll
            for (int o = 1; o < 32; o <<= 1) {
                const int y = __shfl_up_sync(0xffffffffu, x, o);
                if (lane >= o) x += y;
            }
            if (idx <= NGROUP) d_starts[idx] = cum + x - v;   // exclusive
            cum += __shfl_sync(0xffffffffu, x, 31);
        }
        if (lane == 0) d_csDone = 0;          // reset for graph replay
    }
}

// ---------------- K3: stable scatter (4 independent items per thread) -----------
__global__ void __launch_bounds__(256)
scatter_kernel() {
    const int tid = blockIdx.x * blockDim.x + threadIdx.x;
    const int i0 = tid * 4;
    if (i0 >= TOTAL) return;
    const int4 rg4 = __ldg((const int4*)d_rg + tid);        // coalesced 16B
    const int b = i0 >> 9;                                  // same chunk for all 4
    #pragma unroll
    for (int k = 0; k < 4; k++) {
        const int rg = (k == 0) ? rg4.x : (k == 1) ? rg4.y : (k == 2) ? rg4.z : rg4.w;
        const int g = rg >> 16;
        const int pos = d_starts[g] + d_offT[g * NBLK + b] + (rg & 0xffff);
        d_osg[pos] = make_int2(i0 + k, g);
    }
}

// ---------------- K4: main loss ----------------
// All 32 lanes precompute indices/RNG for the warp's 32 sorted positions in
// parallel; the main loop (unroll-4) only streams embedding rows. Positives are
// register-carried (roll-by-1 identity) except at group starts. Only the
// difference (dn - dp) is warp-reduced (1 value per t instead of 2).
__global__ void __launch_bounds__(LOSS_THREADS)
loss_kernel(const float4* __restrict__ emb, float* __restrict__ out) {
    const int lane = threadIdx.x & 31;
    const int warpInBlock = threadIdx.x >> 5;
    const int wid = blockIdx.x * (LOSS_THREADS / 32) + warpInBlock;
    const int lo = wid * CHUNK_T;
    const int valid_total = d_starts[NGROUP];

    // ---- per-lane precompute (all 32 lanes) ----
    int anchor, negi, posi, isStart, validL;
    {
        const int t = lo + lane;
        const int2 og = __ldg(d_osg + t);
        anchor = og.x;
        const int g = og.y;
        const int st = d_starts[g];
        const int cnt = d_counts[g];
        const int np = neg_pos(t, st, cnt, valid_total);
        negi = __ldg(&d_osg[np].x);
        isStart = (t == st);
        const int pIdx = isStart ? (st + cnt - 1) : (t - 1);
        posi = __ldg(&d_osg[pIdx].x);
        validL = (g < NGROUP) && (cnt >= 2) && ((valid_total - cnt) > 0);
    }

    float lsum = 0.0f, wsum = 0.0f;
    float4 aPrev = make_float4(0.f, 0.f, 0.f, 0.f);

    #pragma unroll 1
    for (int tp = 0; tp < CHUNK_T; tp += 4) {
        const unsigned FULL = 0xffffffffu;
        const int a0 = __shfl_sync(FULL, anchor, tp + 0);
        const int a1 = __shfl_sync(FULL, anchor, tp + 1);
        const int a2 = __shfl_sync(FULL, anchor, tp + 2);
        const int a3 = __shfl_sync(FULL, anchor, tp + 3);
        const int q0 = __shfl_sync(FULL, negi, tp + 0);
        const int q1 = __shfl_sync(FULL, negi, tp + 1);
        const int q2 = __shfl_sync(FULL, negi, tp + 2);
        const int q3 = __shfl_sync(FULL, negi, tp + 3);
        const int s0 = __shfl_sync(FULL, isStart, tp + 0);
        const int s1 = __shfl_sync(FULL, isStart, tp + 1);
        const int s2 = __shfl_sync(FULL, isStart, tp + 2);
        const int s3 = __shfl_sync(FULL, isStart, tp + 3);

        const float4 A0 = __ldg(&emb[a0 * 32 + lane]);
        const float4 A1 = __ldg(&emb[a1 * 32 + lane]);
        const float4 A2 = __ldg(&emb[a2 * 32 + lane]);
        const float4 A3 = __ldg(&emb[a3 * 32 + lane]);
        const float4 Q0 = __ldg(&emb[q0 * 32 + lane]);
        const float4 Q1 = __ldg(&emb[q1 * 32 + lane]);
        const float4 Q2 = __ldg(&emb[q2 * 32 + lane]);
        const float4 Q3 = __ldg(&emb[q3 * 32 + lane]);

        float4 P0;
        if (tp == 0 || s0) P0 = __ldg(&emb[__shfl_sync(FULL, posi, tp + 0) * 32 + lane]);
        else               P0 = aPrev;
        float4 P1 = s1 ? __ldg(&emb[__shfl_sync(FULL, posi, tp + 1) * 32 + lane]) : A0;
        float4 P2 = s2 ? __ldg(&emb[__shfl_sync(FULL, posi, tp + 2) * 32 + lane]) : A1;
        float4 P3 = s3 ? __ldg(&emb[__shfl_sync(FULL, posi, tp + 3) * 32 + lane]) : A2;
        aPrev = A3;

        float dp0 = A0.x*P0.x + A0.y*P0.y + A0.z*P0.z + A0.w*P0.w;
        float dn0 = A0.x*Q0.x + A0.y*Q0.y + A0.z*Q0.z + A0.w*Q0.w;
        float dp1 = A1.x*P1.x + A1.y*P1.y + A1.z*P1.z + A1.w*P1.w;
        float dn1 = A1.x*Q1.x + A1.y*Q1.y + A1.z*Q1.z + A1.w*Q1.w;
        float dp2 = A2.x*P2.x + A2.y*P2.y + A2.z*P2.z + A2.w*P2.w;
        float dn2 = A2.x*Q2.x + A2.y*Q2.y + A2.z*Q2.z + A2.w*Q2.w;
        float dp3 = A3.x*P3.x + A3.y*P3.y + A3.z*P3.z + A3.w*P3.w;
        float dn3 = A3.x*Q3.x + A3.y*Q3.y + A3.z*Q3.z + A3.w*Q3.w;

        // reduce only the difference: 1 value per t instead of 2
        float e0 = dn0 - dp0;
        float e1 = dn1 - dp1;
        float e2 = dn2 - dp2;
        float e3 = dn3 - dp3;
        #pragma unroll
        for (int o = 16; o; o >>= 1) {
            e0 += __shfl_xor_sync(FULL, e0, o);
            e1 += __shfl_xor_sync(FULL, e1, o);
            e2 += __shfl_xor_sync(FULL, e2, o);
            e3 += __shfl_xor_sync(FULL, e3, o);
        }

        // lanes 0..3 finish their own t in parallel
        const int vv = __shfl_sync(FULL, validL, tp + (lane & 3));
        if (lane < 4 && vv) {
            float dd = (lane == 0) ? e0 : (lane == 1) ? e1 : (lane == 2) ? e2 : e3;
            dd *= 10.0f;                         // / TEMPERATURE
            lsum += fmaxf(dd, 0.0f) + log1pf(expf(-fabsf(dd)));
            wsum += 1.0f;
        }
    }

    // warp-reduce the lane-distributed sums
    #pragma unroll
    for (int o = 16; o; o >>= 1) {
        lsum += __shfl_xor_sync(0xffffffffu, lsum, o);
        wsum += __shfl_xor_sync(0xffffffffu, wsum, o);
    }

    // deterministic block reduction
    __shared__ float sl[LOSS_THREADS / 32];
    __shared__ float sw[LOSS_THREADS / 32];
    __shared__ int isLast;
    if (lane == 0) { sl[warpInBlock] = lsum; sw[warpInBlock] = wsum; }
    __syncthreads();
    if (threadIdx.x == 0) {
        float L = 0.0f, W = 0.0f;
        #pragma unroll
        for (int i = 0; i < LOSS_THREADS / 32; i++) { L += sl[i]; W += sw[i]; }
        d_partials[2 * blockIdx.x]     = L;
        d_partials[2 * blockIdx.x + 1] = W;
        __threadfence();
        isLast = (atomicAdd(&d_done, 1) == LOSS_BLOCKS - 1);
    }
    __syncthreads();

    // last finishing block does the deterministic final reduction
    if (isLast) {
        __shared__ float fl[256];
        __shared__ float fw[256];
        float L = 0.0f, W = 0.0f;
        for (int i = threadIdx.x; i < LOSS_BLOCKS; i += 256) {
            L += *(volatile float*)(d_partials + 2 * i);
            W += *(volatile float*)(d_partials + 2 * i + 1);
        }
        fl[threadIdx.x] = L; fw[threadIdx.x] = W;
        __syncthreads();
        for (int s = 128; s > 0; s >>= 1) {
            if (threadIdx.x < s) {
                fl[threadIdx.x] += fl[threadIdx.x + s];
                fw[threadIdx.x] += fw[threadIdx.x + s];
            }
            __syncthreads();
        }
        if (threadIdx.x == 0) {
            out[0] = fl[0] / fmaxf(fw[0], 1.0f);
            d_done = 0;                       // reset for graph replay
        }
    }
}

// ---------------- launch ----------------
extern "C" void kernel_launch(void* const* d_in, const int* in_sizes, int n_in,
                              void* d_out, int out_size) {
    const float4* emb   = (const float4*)d_in[0];
    const int*    grp   = (const int*)d_in[1];
    const int*    mask  = (const int*)d_in[2];
    float*        out   = (float*)d_out;
    (void)in_sizes; (void)n_in; (void)out_size;

    rank_kernel<<<NBLK / RANK_WARPS, RANK_WARPS * 32>>>(grp, mask);
    colscan_kernel<<<CSCAN_BLOCKS, 256>>>();
    scatter_kernel<<<TOTAL / 1024, 256>>>();
    loss_kernel<<<LOSS_BLOCKS, LOSS_THREADS>>>(emb, out);
}

// round 10
// speedup vs baseline: 1.1126x; 1.1126x over previous
#include <cuda_runtime.h>
#include <cuda_bf16.h>
#include <stdint.h>

// Problem constants (match reference setup_inputs)
#define TOTAL   262144        // B*N = 16*16384
#define NGROUP  1024          // NUM_GROUPS
#define GSENT   1024          // sentinel group for masked-out nodes
#define NBLK    2048          // number of stable-sort chunks
#define CHUNK   128           // TOTAL / NBLK
#define RANK_WARPS 4          // warps (=chunks) per rank block
#define LOSS_THREADS 256
#define LOSS_BLOCKS  1024     // 8192 warps
#define CHUNK_T      32       // sorted positions per warp
#define CSCAN_BLOCKS ((NGROUP + 1 + 7) / 8)   // 129 blocks of 8 warps

// ---------------- scratch (static __device__, no allocation) ----------------
__device__ int   d_rg[TOTAL];                    // packed (g<<16)|rank
__device__ int   d_histT[(NGROUP + 1) * NBLK];   // [g][b]
__device__ int   d_offT [(NGROUP + 1) * NBLK];   // [g][b] exclusive over b
__device__ int   d_counts[NGROUP + 1];
__device__ int   d_starts[NGROUP + 2];
__device__ int2  d_osg[TOTAL];                   // (orig index, group) per sorted pos
__device__ float d_partials[2 * LOSS_BLOCKS];
__device__ int   d_done;      // zero-init; last loss block resets to 0
__device__ int   d_csDone;    // zero-init; last colscan block resets to 0

// ---------------- threefry2x32 (JAX partitionable mode) ----------------
__device__ __forceinline__ unsigned rotl32(unsigned v, int d) {
    return (v << d) | (v >> (32 - d));
}

__device__ __forceinline__ void threefry2x32(unsigned k0, unsigned k1,
                                             unsigned& x0, unsigned& x1) {
    const unsigned ks0 = k0, ks1 = k1, ks2 = k0 ^ k1 ^ 0x1BD11BDAu;
    x0 += ks0; x1 += ks1;
#define TF_R4(a,b,c,d)                                  \
    x0 += x1; x1 = rotl32(x1, a); x1 ^= x0;             \
    x0 += x1; x1 = rotl32(x1, b); x1 ^= x0;             \
    x0 += x1; x1 = rotl32(x1, c); x1 ^= x0;             \
    x0 += x1; x1 = rotl32(x1, d); x1 ^= x0;
    TF_R4(13,15,26, 6); x0 += ks1; x1 += ks2 + 1u;
    TF_R4(17,29,16,24); x0 += ks2; x1 += ks0 + 2u;
    TF_R4(13,15,26, 6); x0 += ks0; x1 += ks1 + 3u;
    TF_R4(17,29,16,24); x0 += ks1; x1 += ks2 + 4u;
    TF_R4(13,15,26, 6); x0 += ks2; x1 += ks0 + 5u;
#undef TF_R4
}

// u[t]: counter = 64-bit flat index -> (hi=0, lo=t); draw = fold(out0^out1).
__device__ __forceinline__ float jax_uniform_at(int t) {
    unsigned x0 = 0u;
    unsigned x1 = (unsigned)t;
    threefry2x32(0u, 42u, x0, x1);       // jax.random.key(42) -> (0, 42)
    const unsigned bits = x0 ^ x1;
    return __uint_as_float((bits >> 9) | 0x3f800000u) - 1.0f;
}

// negative sorted-position for sorted index t
__device__ __forceinline__ int neg_pos(int t, int st, int cnt, int valid_total) {
    const float u = jax_uniform_at(t);
    const int comp = max(valid_total - cnt, 1);
    int r = (int)(u * (float)comp);
    if (r > comp - 1) r = comp - 1;
    int np_ = (r < st) ? r : r + cnt;
    if (np_ < 0) np_ = 0;
    if (np_ > TOTAL - 1) np_ = TOTAL - 1;
    return np_;
}

// ---------------- K1: stable per-chunk rank + per-chunk histogram ----------------
// One warp per 128-element chunk (2048 chunks -> 4x the TLP of the 512-chunk
// version). The block's 4 warps cover 4 consecutive chunks, so histT rows are
// written cooperatively as int4 (coalesced-ish 16B stores).
__global__ void __launch_bounds__(RANK_WARPS * 32)
rank_kernel(const int* __restrict__ groups, const int* __restrict__ mask) {
    __shared__ int bins[RANK_WARPS][NGROUP + 1];
    const int warpId = threadIdx.x >> 5;
    const int lane = threadIdx.x & 31;
    const int b = blockIdx.x * RANK_WARPS + warpId;       // chunk id 0..2047
    int* myb = bins[warpId];
    for (int i = lane; i <= NGROUP; i += 32) myb[i] = 0;
    __syncwarp();
    const int base = b * CHUNK;
    #pragma unroll
    for (int j = 0; j < CHUNK; j += 32) {
        const int i = base + j + lane;
        const int g = mask[i] ? groups[i] : GSENT;
        const unsigned m = __match_any_sync(0xffffffffu, g);
        const int rankInWarp = __popc(m & ((1u << lane) - 1u));
        const int leader = __ffs(m) - 1;
        int baseBin = 0;
        if (lane == leader) baseBin = atomicAdd(&myb[g], __popc(m));
        baseBin = __shfl_sync(0xffffffffu, baseBin, leader);
        d_rg[i] = (g << 16) | (baseBin + rankInWarp);
        __syncwarp();
    }
    __syncthreads();
    // cooperative histT write: 4 consecutive chunk slots per group -> int4
    const int b0 = blockIdx.x * RANK_WARPS;
    for (int g = threadIdx.x; g <= NGROUP; g += RANK_WARPS * 32) {
        int4 v = make_int4(bins[0][g], bins[1][g], bins[2][g], bins[3][g]);
        *(int4*)(d_histT + g * NBLK + b0) = v;
    }
}

// ---------------- K2: per-group scan over chunks + fused starts scan ------------
__global__ void __launch_bounds__(256)
colscan_kernel() {
    const int warpId = threadIdx.x >> 5;
    const int lane = threadIdx.x & 31;
    const int g = blockIdx.x * 8 + warpId;
    if (g <= NGROUP) {
        const int baseIdx = g * NBLK;
        int cum = 0;
        #pragma unroll 4
        for (int b0 = 0; b0 < NBLK; b0 += 32) {
            const int h = d_histT[baseIdx + b0 + lane];     // coalesced 128B
            int x = h;
            #pragma unroll
            for (int o = 1; o < 32; o <<= 1) {
                const int y = __shfl_up_sync(0xffffffffu, x, o);
                if (lane >= o) x += y;
            }
            d_offT[baseIdx + b0 + lane] = cum + x - h;      // exclusive
            cum += __shfl_sync(0xffffffffu, x, 31);
        }
        if (lane == 0) d_counts[g] = cum;
    }
    // ---- fused starts: last finishing block's warp 0 scans counts ----
    __shared__ int isLast;
    __syncthreads();
    if (threadIdx.x == 0) {
        __threadfence();
        isLast = (atomicAdd(&d_csDone, 1) == CSCAN_BLOCKS - 1);
    }
    __syncthreads();
    if (isLast && warpId == 0) {
        int cum = 0;
        #pragma unroll 1
        for (int b0 = 0; b0 <= NGROUP; b0 += 32) {
            const int idx = b0 + lane;
            // volatile: other SMs wrote counts; bypass potentially-stale L1
            const int v = (idx <= NGROUP) ? *(volatile int*)(d_counts + idx) : 0;
            int x = v;
            #pragma unroll
            for (int o = 1; o < 32; o <<= 1) {
                const int y = __shfl_up_sync(0xffffffffu, x, o);
                if (lane >= o) x += y;
            }
            if (idx <= NGROUP) d_starts[idx] = cum + x - v;   // exclusive
            cum += __shfl_sync(0xffffffffu, x, 31);
        }
        if (lane == 0) d_csDone = 0;          // reset for graph replay
    }
}

// ---------------- K3: stable scatter (full TLP: one item per thread) ------------
__global__ void __launch_bounds__(256)
scatter_kernel() {
    const int i = blockIdx.x * blockDim.x + threadIdx.x;
    if (i >= TOTAL) return;
    const int rg = d_rg[i];
    const int g = rg >> 16;
    const int b = i >> 7;                     // i / CHUNK (CHUNK = 128)
    const int pos = d_starts[g] + d_offT[g * NBLK + b] + (rg & 0xffff);
    d_osg[pos] = make_int2(i, g);
}

// ---------------- K4: main loss (R8-proven version, verbatim) ----------------
// All 32 lanes precompute indices/RNG for the warp's 32 sorted positions in
// parallel; the main loop (unroll-4) only streams embedding rows. Positives are
// register-carried (roll-by-1 identity) except at group starts.
__global__ void __launch_bounds__(LOSS_THREADS)
loss_kernel(const float4* __restrict__ emb, float* __restrict__ out) {
    const int lane = threadIdx.x & 31;
    const int warpInBlock = threadIdx.x >> 5;
    const int wid = blockIdx.x * (LOSS_THREADS / 32) + warpInBlock;
    const int lo = wid * CHUNK_T;
    const int valid_total = d_starts[NGROUP];

    // ---- per-lane precompute (all 32 lanes) ----
    int anchor, negi, posi, isStart, validL;
    {
        const int t = lo + lane;
        const int2 og = __ldg(d_osg + t);
        anchor = og.x;
        const int g = og.y;
        const int st = d_starts[g];
        const int cnt = d_counts[g];
        const int np = neg_pos(t, st, cnt, valid_total);
        negi = __ldg(&d_osg[np].x);
        isStart = (t == st);
        const int pIdx = isStart ? (st + cnt - 1) : (t - 1);
        posi = __ldg(&d_osg[pIdx].x);
        validL = (g < NGROUP) && (cnt >= 2) && ((valid_total - cnt) > 0);
    }

    float lsum = 0.0f, wsum = 0.0f;
    float4 aPrev = make_float4(0.f, 0.f, 0.f, 0.f);

    #pragma unroll 1
    for (int tp = 0; tp < CHUNK_T; tp += 4) {
        const unsigned FULL = 0xffffffffu;
        const int a0 = __shfl_sync(FULL, anchor, tp + 0);
        const int a1 = __shfl_sync(FULL, anchor, tp + 1);
        const int a2 = __shfl_sync(FULL, anchor, tp + 2);
        const int a3 = __shfl_sync(FULL, anchor, tp + 3);
        const int q0 = __shfl_sync(FULL, negi, tp + 0);
        const int q1 = __shfl_sync(FULL, negi, tp + 1);
        const int q2 = __shfl_sync(FULL, negi, tp + 2);
        const int q3 = __shfl_sync(FULL, negi, tp + 3);
        const int s0 = __shfl_sync(FULL, isStart, tp + 0);
        const int s1 = __shfl_sync(FULL, isStart, tp + 1);
        const int s2 = __shfl_sync(FULL, isStart, tp + 2);
        const int s3 = __shfl_sync(FULL, isStart, tp + 3);

        const float4 A0 = __ldg(&emb[a0 * 32 + lane]);
        const float4 A1 = __ldg(&emb[a1 * 32 + lane]);
        const float4 A2 = __ldg(&emb[a2 * 32 + lane]);
        const float4 A3 = __ldg(&emb[a3 * 32 + lane]);
        const float4 Q0 = __ldg(&emb[q0 * 32 + lane]);
        const float4 Q1 = __ldg(&emb[q1 * 32 + lane]);
        const float4 Q2 = __ldg(&emb[q2 * 32 + lane]);
        const float4 Q3 = __ldg(&emb[q3 * 32 + lane]);

        float4 P0;
        if (tp == 0 || s0) P0 = __ldg(&emb[__shfl_sync(FULL, posi, tp + 0) * 32 + lane]);
        else               P0 = aPrev;
        float4 P1 = s1 ? __ldg(&emb[__shfl_sync(FULL, posi, tp + 1) * 32 + lane]) : A0;
        float4 P2 = s2 ? __ldg(&emb[__shfl_sync(FULL, posi, tp + 2) * 32 + lane]) : A1;
        float4 P3 = s3 ? __ldg(&emb[__shfl_sync(FULL, posi, tp + 3) * 32 + lane]) : A2;
        aPrev = A3;

        float dp0 = A0.x*P0.x + A0.y*P0.y + A0.z*P0.z + A0.w*P0.w;
        float dn0 = A0.x*Q0.x + A0.y*Q0.y + A0.z*Q0.z + A0.w*Q0.w;
        float dp1 = A1.x*P1.x + A1.y*P1.y + A1.z*P1.z + A1.w*P1.w;
        float dn1 = A1.x*Q1.x + A1.y*Q1.y + A1.z*Q1.z + A1.w*Q1.w;
        float dp2 = A2.x*P2.x + A2.y*P2.y + A2.z*P2.z + A2.w*P2.w;
        float dn2 = A2.x*Q2.x + A2.y*Q2.y + A2.z*Q2.z + A2.w*Q2.w;
        float dp3 = A3.x*P3.x + A3.y*P3.y + A3.z*P3.z + A3.w*P3.w;
        float dn3 = A3.x*Q3.x + A3.y*Q3.y + A3.z*Q3.z + A3.w*Q3.w;
        #pragma unroll
        for (int o = 16; o; o >>= 1) {
            dp0 += __shfl_xor_sync(FULL, dp0, o);
            dn0 += __shfl_xor_sync(FULL, dn0, o);
            dp1 += __shfl_xor_sync(FULL, dp1, o);
            dn1 += __shfl_xor_sync(FULL, dn1, o);
            dp2 += __shfl_xor_sync(FULL, dp2, o);
            dn2 += __shfl_xor_sync(FULL, dn2, o);
            dp3 += __shfl_xor_sync(FULL, dp3, o);
            dn3 += __shfl_xor_sync(FULL, dn3, o);
        }

        // lanes 0..3 finish their own t in parallel
        const int vv = __shfl_sync(FULL, validL, tp + (lane & 3));
        if (lane < 4 && vv) {
            float dd;
            if      (lane == 0) dd = dn0 - dp0;
            else if (lane == 1) dd = dn1 - dp1;
            else if (lane == 2) dd = dn2 - dp2;
            else                dd = dn3 - dp3;
            dd *= 10.0f;                         // / TEMPERATURE
            lsum += fmaxf(dd, 0.0f) + log1pf(expf(-fabsf(dd)));
            wsum += 1.0f;
        }
    }

    // warp-reduce the lane-distributed sums
    #pragma unroll
    for (int o = 16; o; o >>= 1) {
        lsum += __shfl_xor_sync(0xffffffffu, lsum, o);
        wsum += __shfl_xor_sync(0xffffffffu, wsum, o);
    }

    // deterministic block reduction
    __shared__ float sl[LOSS_THREADS / 32];
    __shared__ float sw[LOSS_THREADS / 32];
    __shared__ int isLast;
    if (lane == 0) { sl[warpInBlock] = lsum; sw[warpInBlock] = wsum; }
    __syncthreads();
    if (threadIdx.x == 0) {
        float L = 0.0f, W = 0.0f;
        #pragma unroll
        for (int i = 0; i < LOSS_THREADS / 32; i++) { L += sl[i]; W += sw[i]; }
        d_partials[2 * blockIdx.x]     = L;
        d_partials[2 * blockIdx.x + 1] = W;
        __threadfence();
        isLast = (atomicAdd(&d_done, 1) == LOSS_BLOCKS - 1);
    }
    __syncthreads();

    // last finishing block does the deterministic final reduction
    if (isLast) {
        __shared__ float fl[256];
        __shared__ float fw[256];
        float L = 0.0f, W = 0.0f;
        for (int i = threadIdx.x; i < LOSS_BLOCKS; i += 256) {
            L += *(volatile float*)(d_partials + 2 * i);
            W += *(volatile float*)(d_partials + 2 * i + 1);
        }
        fl[threadIdx.x] = L; fw[threadIdx.x] = W;
        __syncthreads();
        for (int s = 128; s > 0; s >>= 1) {
            if (threadIdx.x < s) {
                fl[threadIdx.x] += fl[threadIdx.x + s];
                fw[threadIdx.x] += fw[threadIdx.x + s];
            }
            __syncthreads();
        }
        if (threadIdx.x == 0) {
            out[0] = fl[0] / fmaxf(fw[0], 1.0f);
            d_done = 0;                       // reset for graph replay
        }
    }
}

// ---------------- launch ----------------
extern "C" void kernel_launch(void* const* d_in, const int* in_sizes, int n_in,
                              void* d_out, int out_size) {
    const float4* emb   = (const float4*)d_in[0];
    const int*    grp   = (const int*)d_in[1];
    const int*    mask  = (const int*)d_in[2];
    float*        out   = (float*)d_out;
    (void)in_sizes; (void)n_in; (void)out_size;

    rank_kernel<<<NBLK / RANK_WARPS, RANK_WARPS * 32>>>(grp, mask);
    colscan_kernel<<<CSCAN_BLOCKS, 256>>>();
    scatter_kernel<<<TOTAL / 256, 256>>>();
    loss_kernel<<<LOSS_BLOCKS, LOSS_THREADS>>>(emb, out);
}

// round 11
// speedup vs baseline: 1.1155x; 1.0027x over previous
#include <cuda_runtime.h>
#include <cuda_bf16.h>
#include <stdint.h>

// Problem constants (match reference setup_inputs)
#define TOTAL   262144        // B*N = 16*16384
#define NGROUP  1024          // NUM_GROUPS
#define GSENT   1024          // sentinel group for masked-out nodes
#define NBLK    512           // number of stable-sort chunks
#define CHUNK   512           // TOTAL / NBLK
#define NB_SORT 512           // fused sort kernel blocks (all resident: >=6/SM capacity)
#define SORT_THREADS 256
#define LOSS_THREADS 256
#define LOSS_BLOCKS  1024     // 8192 warps
#define CHUNK_T      32       // sorted positions per warp

// ---------------- scratch (static __device__, no allocation) ----------------
__device__ int   d_rg[TOTAL];                    // packed (g<<16)|rank
__device__ int   d_histT[(NGROUP + 1) * NBLK];   // [g][b]
__device__ int   d_offT [(NGROUP + 1) * NBLK];   // [g][b] exclusive over b
__device__ int   d_counts[NGROUP + 1];
__device__ int   d_starts[NGROUP + 2];
__device__ int2  d_osg[TOTAL];                   // (orig index, group) per sorted pos
__device__ float d_partials[2 * LOSS_BLOCKS];
__device__ int   d_done;      // zero-init; last loss block resets to 0
__device__ int   g_bar;       // zero-init; sort kernel resets to 0 at exit

// ---------------- grid barrier (monotonic count, self-resetting) ----------------
__device__ __forceinline__ void grid_barrier(int phase) {
    __syncthreads();
    if (threadIdx.x == 0) {
        __threadfence();
        atomicAdd(&g_bar, 1);
        while (*(volatile int*)&g_bar < phase * NB_SORT) { }
        __threadfence();
    }
    __syncthreads();
}

// ---------------- threefry2x32 (JAX partitionable mode) ----------------
__device__ __forceinline__ unsigned rotl32(unsigned v, int d) {
    return (v << d) | (v >> (32 - d));
}

__device__ __forceinline__ void threefry2x32(unsigned k0, unsigned k1,
                                             unsigned& x0, unsigned& x1) {
    const unsigned ks0 = k0, ks1 = k1, ks2 = k0 ^ k1 ^ 0x1BD11BDAu;
    x0 += ks0; x1 += ks1;
#define TF_R4(a,b,c,d)                                  \
    x0 += x1; x1 = rotl32(x1, a); x1 ^= x0;             \
    x0 += x1; x1 = rotl32(x1, b); x1 ^= x0;             \
    x0 += x1; x1 = rotl32(x1, c); x1 ^= x0;             \
    x0 += x1; x1 = rotl32(x1, d); x1 ^= x0;
    TF_R4(13,15,26, 6); x0 += ks1; x1 += ks2 + 1u;
    TF_R4(17,29,16,24); x0 += ks2; x1 += ks0 + 2u;
    TF_R4(13,15,26, 6); x0 += ks0; x1 += ks1 + 3u;
    TF_R4(17,29,16,24); x0 += ks1; x1 += ks2 + 4u;
    TF_R4(13,15,26, 6); x0 += ks2; x1 += ks0 + 5u;
#undef TF_R4
}

// u[t]: counter = 64-bit flat index -> (hi=0, lo=t); draw = fold(out0^out1).
__device__ __forceinline__ float jax_uniform_at(int t) {
    unsigned x0 = 0u;
    unsigned x1 = (unsigned)t;
    threefry2x32(0u, 42u, x0, x1);       // jax.random.key(42) -> (0, 42)
    const unsigned bits = x0 ^ x1;
    return __uint_as_float((bits >> 9) | 0x3f800000u) - 1.0f;
}

// negative sorted-position for sorted index t
__device__ __forceinline__ int neg_pos(int t, int st, int cnt, int valid_total) {
    const float u = jax_uniform_at(t);
    const int comp = max(valid_total - cnt, 1);
    int r = (int)(u * (float)comp);
    if (r > comp - 1) r = comp - 1;
    int np_ = (r < st) ? r : r + cnt;
    if (np_ < 0) np_ = 0;
    if (np_ > TOTAL - 1) np_ = TOTAL - 1;
    return np_;
}

// ---------------- K1: fused stable counting sort ----------------
// Phase TLP matches the R8 separate-kernel versions; fusion only removes the
// launch gaps. Block b's warp 0 ranks chunk b; colscan spreads groups across
// blocks; scatter uses all threads with 2 strided independent items.
__global__ void __launch_bounds__(SORT_THREADS)
sort_kernel(const int* __restrict__ groups, const int* __restrict__ mask) {
    __shared__ int bins[NGROUP + 1];
    const int warpId = threadIdx.x >> 5;
    const int lane = threadIdx.x & 31;
    const int b = blockIdx.x;                       // chunk id 0..511

    // ---- phase 1: per-chunk stable rank + histogram (warp 0 of each block) ----
    for (int i = threadIdx.x; i <= NGROUP; i += SORT_THREADS) bins[i] = 0;
    __syncthreads();
    if (warpId == 0) {
        const int base = b * CHUNK;
        for (int j = 0; j < CHUNK; j += 32) {
            const int i = base + j + lane;
            const int g = mask[i] ? groups[i] : GSENT;
            const unsigned m = __match_any_sync(0xffffffffu, g);
            const int rankInWarp = __popc(m & ((1u << lane) - 1u));
            const int leader = __ffs(m) - 1;
            int baseBin = 0;
            if (lane == leader) baseBin = atomicAdd(&bins[g], __popc(m));
            baseBin = __shfl_sync(0xffffffffu, baseBin, leader);
            d_rg[i] = (g << 16) | (baseBin + rankInWarp);
            __syncwarp();
        }
    }
    __syncthreads();
    for (int g = threadIdx.x; g <= NGROUP; g += SORT_THREADS)
        d_histT[g * NBLK + b] = bins[g];
    grid_barrier(1);

    // ---- phase 2: per-group scan over chunks (spread: w0->g=b, w1->g=b+512) ----
    {
        int g = -1;
        if (warpId == 0) g = b;
        else if (warpId == 1) g = b + 512;
        else if (warpId == 2 && b == 0) g = NGROUP;    // group 1024 (sentinel)
        if (g >= 0 && g <= NGROUP) {
            const int baseIdx = g * NBLK;
            int cum = 0;
            #pragma unroll
            for (int b0 = 0; b0 < NBLK; b0 += 32) {
                const int h = d_histT[baseIdx + b0 + lane];   // coalesced 128B
                int x = h;
                #pragma unroll
                for (int o = 1; o < 32; o <<= 1) {
                    const int y = __shfl_up_sync(0xffffffffu, x, o);
                    if (lane >= o) x += y;
                }
                d_offT[baseIdx + b0 + lane] = cum + x - h;    // exclusive
                cum += __shfl_sync(0xffffffffu, x, 31);
            }
            if (lane == 0) d_counts[g] = cum;
        }
    }
    grid_barrier(2);

    // ---- phase 3: exclusive scan of counts -> starts (block 0, warp 0) ----
    if (b == 0 && warpId == 0) {
        int cum = 0;
        #pragma unroll 1
        for (int b0 = 0; b0 <= NGROUP; b0 += 32) {
            const int idx = b0 + lane;
            // volatile: other SMs wrote counts
            const int v = (idx <= NGROUP) ? *(volatile int*)(d_counts + idx) : 0;
            int x = v;
            #pragma unroll
            for (int o = 1; o < 32; o <<= 1) {
                const int y = __shfl_up_sync(0xffffffffu, x, o);
                if (lane >= o) x += y;
            }
            if (idx <= NGROUP) d_starts[idx] = cum + x - v;   // exclusive
            cum += __shfl_sync(0xffffffffu, x, 31);
        }
    }
    grid_barrier(3);

    // ---- phase 4: stable scatter (2 strided independent items per thread) ----
    {
        const int tid = b * SORT_THREADS + threadIdx.x;       // 0..131071
        #pragma unroll
        for (int k = 0; k < 2; k++) {
            const int i = tid + k * (NB_SORT * SORT_THREADS);
            const int rg = d_rg[i];
            const int g = rg >> 16;
            const int cb = i >> 9;                            // i / CHUNK
            const int pos = d_starts[g] + d_offT[g * NBLK + cb] + (rg & 0xffff);
            d_osg[pos] = make_int2(i, g);
        }
    }

    // final arrival: last arriver resets the barrier for graph replay
    __syncthreads();
    if (threadIdx.x == 0) {
        __threadfence();
        if (atomicAdd(&g_bar, 1) == 4 * NB_SORT - 1) g_bar = 0;
    }
}

// ---------------- K2: main loss (R8-proven version, verbatim) ----------------
__global__ void __launch_bounds__(LOSS_THREADS)
loss_kernel(const float4* __restrict__ emb, float* __restrict__ out) {
    const int lane = threadIdx.x & 31;
    const int warpInBlock = threadIdx.x >> 5;
    const int wid = blockIdx.x * (LOSS_THREADS / 32) + warpInBlock;
    const int lo = wid * CHUNK_T;
    const int valid_total = d_starts[NGROUP];

    // ---- per-lane precompute (all 32 lanes) ----
    int anchor, negi, posi, isStart, validL;
    {
        const int t = lo + lane;
        const int2 og = __ldg(d_osg + t);
        anchor = og.x;
        const int g = og.y;
        const int st = d_starts[g];
        const int cnt = d_counts[g];
        const int np = neg_pos(t, st, cnt, valid_total);
        negi = __ldg(&d_osg[np].x);
        isStart = (t == st);
        const int pIdx = isStart ? (st + cnt - 1) : (t - 1);
        posi = __ldg(&d_osg[pIdx].x);
        validL = (g < NGROUP) && (cnt >= 2) && ((valid_total - cnt) > 0);
    }

    float lsum = 0.0f, wsum = 0.0f;
    float4 aPrev = make_float4(0.f, 0.f, 0.f, 0.f);

    #pragma unroll 1
    for (int tp = 0; tp < CHUNK_T; tp += 4) {
        const unsigned FULL = 0xffffffffu;
        const int a0 = __shfl_sync(FULL, anchor, tp + 0);
        const int a1 = __shfl_sync(FULL, anchor, tp + 1);
        const int a2 = __shfl_sync(FULL, anchor, tp + 2);
        const int a3 = __shfl_sync(FULL, anchor, tp + 3);
        const int q0 = __shfl_sync(FULL, negi, tp + 0);
        const int q1 = __shfl_sync(FULL, negi, tp + 1);
        const int q2 = __shfl_sync(FULL, negi, tp + 2);
        const int q3 = __shfl_sync(FULL, negi, tp + 3);
        const int s0 = __shfl_sync(FULL, isStart, tp + 0);
        const int s1 = __shfl_sync(FULL, isStart, tp + 1);
        const int s2 = __shfl_sync(FULL, isStart, tp + 2);
        const int s3 = __shfl_sync(FULL, isStart, tp + 3);

        const float4 A0 = __ldg(&emb[a0 * 32 + lane]);
        const float4 A1 = __ldg(&emb[a1 * 32 + lane]);
        const float4 A2 = __ldg(&emb[a2 * 32 + lane]);
        const float4 A3 = __ldg(&emb[a3 * 32 + lane]);
        const float4 Q0 = __ldg(&emb[q0 * 32 + lane]);
        const float4 Q1 = __ldg(&emb[q1 * 32 + lane]);
        const float4 Q2 = __ldg(&emb[q2 * 32 + lane]);
        const float4 Q3 = __ldg(&emb[q3 * 32 + lane]);

        float4 P0;
        if (tp == 0 || s0) P0 = __ldg(&emb[__shfl_sync(FULL, posi, tp + 0) * 32 + lane]);
        else               P0 = aPrev;
        float4 P1 = s1 ? __ldg(&emb[__shfl_sync(FULL, posi, tp + 1) * 32 + lane]) : A0;
        float4 P2 = s2 ? __ldg(&emb[__shfl_sync(FULL, posi, tp + 2) * 32 + lane]) : A1;
        float4 P3 = s3 ? __ldg(&emb[__shfl_sync(FULL, posi, tp + 3) * 32 + lane]) : A2;
        aPrev = A3;

        float dp0 = A0.x*P0.x + A0.y*P0.y + A0.z*P0.z + A0.w*P0.w;
        float dn0 = A0.x*Q0.x + A0.y*Q0.y + A0.z*Q0.z + A0.w*Q0.w;
        float dp1 = A1.x*P1.x + A1.y*P1.y + A1.z*P1.z + A1.w*P1.w;
        float dn1 = A1.x*Q1.x + A1.y*Q1.y + A1.z*Q1.z + A1.w*Q1.w;
        float dp2 = A2.x*P2.x + A2.y*P2.y + A2.z*P2.z + A2.w*P2.w;
        float dn2 = A2.x*Q2.x + A2.y*Q2.y + A2.z*Q2.z + A2.w*Q2.w;
        float dp3 = A3.x*P3.x + A3.y*P3.y + A3.z*P3.z + A3.w*P3.w;
        float dn3 = A3.x*Q3.x + A3.y*Q3.y + A3.z*Q3.z + A3.w*Q3.w;
        #pragma unroll
        for (int o = 16; o; o >>= 1) {
            dp0 += __shfl_xor_sync(FULL, dp0, o);
            dn0 += __shfl_xor_sync(FULL, dn0, o);
            dp1 += __shfl_xor_sync(FULL, dp1, o);
            dn1 += __shfl_xor_sync(FULL, dn1, o);
            dp2 += __shfl_xor_sync(FULL, dp2, o);
            dn2 += __shfl_xor_sync(FULL, dn2, o);
            dp3 += __shfl_xor_sync(FULL, dp3, o);
            dn3 += __shfl_xor_sync(FULL, dn3, o);
        }

        // lanes 0..3 finish their own t in parallel
        const int vv = __shfl_sync(FULL, validL, tp + (lane & 3));
        if (lane < 4 && vv) {
            float dd;
            if      (lane == 0) dd = dn0 - dp0;
            else if (lane == 1) dd = dn1 - dp1;
            else if (lane == 2) dd = dn2 - dp2;
            else                dd = dn3 - dp3;
            dd *= 10.0f;                         // / TEMPERATURE
            lsum += fmaxf(dd, 0.0f) + log1pf(expf(-fabsf(dd)));
            wsum += 1.0f;
        }
    }

    // warp-reduce the lane-distributed sums
    #pragma unroll
    for (int o = 16; o; o >>= 1) {
        lsum += __shfl_xor_sync(0xffffffffu, lsum, o);
        wsum += __shfl_xor_sync(0xffffffffu, wsum, o);
    }

    // deterministic block reduction
    __shared__ float sl[LOSS_THREADS / 32];
    __shared__ float sw[LOSS_THREADS / 32];
    __shared__ int isLast;
    if (lane == 0) { sl[warpInBlock] = lsum; sw[warpInBlock] = wsum; }
    __syncthreads();
    if (threadIdx.x == 0) {
        float L = 0.0f, W = 0.0f;
        #pragma unroll
        for (int i = 0; i < LOSS_THREADS / 32; i++) { L += sl[i]; W += sw[i]; }
        d_partials[2 * blockIdx.x]     = L;
        d_partials[2 * blockIdx.x + 1] = W;
        __threadfence();
        isLast = (atomicAdd(&d_done, 1) == LOSS_BLOCKS - 1);
    }
    __syncthreads();

    // last finishing block does the deterministic final reduction
    if (isLast) {
        __shared__ float fl[256];
        __shared__ float fw[256];
        float L = 0.0f, W = 0.0f;
        for (int i = threadIdx.x; i < LOSS_BLOCKS; i += 256) {
            L += *(volatile float*)(d_partials + 2 * i);
            W += *(volatile float*)(d_partials + 2 * i + 1);
        }
        fl[threadIdx.x] = L; fw[threadIdx.x] = W;
        __syncthreads();
        for (int s = 128; s > 0; s >>= 1) {
            if (threadIdx.x < s) {
                fl[threadIdx.x] += fl[threadIdx.x + s];
                fw[threadIdx.x] += fw[threadIdx.x + s];
            }
            __syncthreads();
        }
        if (threadIdx.x == 0) {
            out[0] = fl[0] / fmaxf(fw[0], 1.0f);
            d_done = 0;                       // reset for graph replay
        }
    }
}

// ---------------- launch ----------------
extern "C" void kernel_launch(void* const* d_in, const int* in_sizes, int n_in,
                              void* d_out, int out_size) {
    const float4* emb   = (const float4*)d_in[0];
    const int*    grp   = (const int*)d_in[1];
    const int*    mask  = (const int*)d_in[2];
    float*        out   = (float*)d_out;
    (void)in_sizes; (void)n_in; (void)out_size;

    sort_kernel<<<NB_SORT, SORT_THREADS>>>(grp, mask);
    loss_kernel<<<LOSS_BLOCKS, LOSS_THREADS>>>(emb, out);
}

// round 12
// speedup vs baseline: 1.2400x; 1.1116x over previous
#include <cuda_runtime.h>
#include <cuda_bf16.h>
#include <stdint.h>

// Problem constants (match reference setup_inputs)
#define TOTAL   262144        // B*N = 16*16384
#define NGROUP  1024          // NUM_GROUPS
#define GSENT   1024          // sentinel group for masked-out nodes
#define NBLK    512           // number of stable-sort chunks
#define CHUNK   512           // TOTAL / NBLK
#define RANK_WARPS 4          // warps (=chunks) per rank block
#define LOSS_THREADS 256
#define LOSS_BLOCKS  1024
#define CHUNK_T      32       // sorted positions per warp-chunk
#define NWCHUNKS     (TOTAL / CHUNK_T)          // 8192 warp-chunks
#define CSCAN_BLOCKS ((NGROUP + 1 + 7) / 8)     // 129 blocks of 8 warps

// ---------------- scratch (static __device__, no allocation) ----------------
__device__ int   d_rg[TOTAL];                    // packed (g<<16)|rank
__device__ int   d_histT[(NGROUP + 1) * NBLK];   // [g][b]
__device__ int   d_offT [(NGROUP + 1) * NBLK];   // [g][b] exclusive over b
__device__ int   d_counts[NGROUP + 1];
__device__ int   d_starts[NGROUP + 2];
__device__ int2  d_osg[TOTAL];                   // (orig index, group) per sorted pos
__device__ float d_partials[2 * LOSS_BLOCKS];
__device__ int   d_done;      // zero-init; last loss block resets to 0
__device__ int   d_csDone;    // zero-init; last colscan block resets to 0
__device__ int   d_work;      // zero-init; loss work-stealing counter, reset by last block

// ---------------- threefry2x32 (JAX partitionable mode) ----------------
__device__ __forceinline__ unsigned rotl32(unsigned v, int d) {
    return (v << d) | (v >> (32 - d));
}

__device__ __forceinline__ void threefry2x32(unsigned k0, unsigned k1,
                                             unsigned& x0, unsigned& x1) {
    const unsigned ks0 = k0, ks1 = k1, ks2 = k0 ^ k1 ^ 0x1BD11BDAu;
    x0 += ks0; x1 += ks1;
#define TF_R4(a,b,c,d)                                  \
    x0 += x1; x1 = rotl32(x1, a); x1 ^= x0;             \
    x0 += x1; x1 = rotl32(x1, b); x1 ^= x0;             \
    x0 += x1; x1 = rotl32(x1, c); x1 ^= x0;             \
    x0 += x1; x1 = rotl32(x1, d); x1 ^= x0;
    TF_R4(13,15,26, 6); x0 += ks1; x1 += ks2 + 1u;
    TF_R4(17,29,16,24); x0 += ks2; x1 += ks0 + 2u;
    TF_R4(13,15,26, 6); x0 += ks0; x1 += ks1 + 3u;
    TF_R4(17,29,16,24); x0 += ks1; x1 += ks2 + 4u;
    TF_R4(13,15,26, 6); x0 += ks2; x1 += ks0 + 5u;
#undef TF_R4
}

// u[t]: counter = 64-bit flat index -> (hi=0, lo=t); draw = fold(out0^out1).
__device__ __forceinline__ float jax_uniform_at(int t) {
    unsigned x0 = 0u;
    unsigned x1 = (unsigned)t;
    threefry2x32(0u, 42u, x0, x1);       // jax.random.key(42) -> (0, 42)
    const unsigned bits = x0 ^ x1;
    return __uint_as_float((bits >> 9) | 0x3f800000u) - 1.0f;
}

// negative sorted-position for sorted index t
__device__ __forceinline__ int neg_pos(int t, int st, int cnt, int valid_total) {
    const float u = jax_uniform_at(t);
    const int comp = max(valid_total - cnt, 1);
    int r = (int)(u * (float)comp);
    if (r > comp - 1) r = comp - 1;
    int np_ = (r < st) ? r : r + cnt;
    if (np_ < 0) np_ = 0;
    if (np_ > TOTAL - 1) np_ = TOTAL - 1;
    return np_;
}

// ---------------- K1: stable per-chunk rank + per-chunk histogram ----------------
__global__ void __launch_bounds__(RANK_WARPS * 32)
rank_kernel(const int* __restrict__ groups, const int* __restrict__ mask) {
    __shared__ int bins[RANK_WARPS][NGROUP + 1];
    const int warpId = threadIdx.x >> 5;
    const int lane = threadIdx.x & 31;
    const int b = blockIdx.x * RANK_WARPS + warpId;       // chunk id 0..511
    int* myb = bins[warpId];
    for (int i = lane; i <= NGROUP; i += 32) myb[i] = 0;
    __syncwarp();
    const int base = b * CHUNK;
    for (int j = 0; j < CHUNK; j += 32) {
        const int i = base + j + lane;
        const int g = mask[i] ? groups[i] : GSENT;
        const unsigned m = __match_any_sync(0xffffffffu, g);
        const int rankInWarp = __popc(m & ((1u << lane) - 1u));
        const int leader = __ffs(m) - 1;
        int baseBin = 0;
        if (lane == leader) baseBin = atomicAdd(&myb[g], __popc(m));
        baseBin = __shfl_sync(0xffffffffu, baseBin, leader);
        d_rg[i] = (g << 16) | (baseBin + rankInWarp);
        __syncwarp();
    }
    for (int i = lane; i <= NGROUP; i += 32) d_histT[i * NBLK + b] = myb[i];
}

// ---------------- K2: per-group scan over chunks + fused starts scan ------------
__global__ void __launch_bounds__(256)
colscan_kernel() {
    const int warpId = threadIdx.x >> 5;
    const int lane = threadIdx.x & 31;
    const int g = blockIdx.x * 8 + warpId;
    if (g <= NGROUP) {
        const int baseIdx = g * NBLK;
        int cum = 0;
        #pragma unroll
        for (int b0 = 0; b0 < NBLK; b0 += 32) {
            const int h = d_histT[baseIdx + b0 + lane];     // coalesced 128B
            int x = h;
            #pragma unroll
            for (int o = 1; o < 32; o <<= 1) {
                const int y = __shfl_up_sync(0xffffffffu, x, o);
                if (lane >= o) x += y;
            }
            d_offT[baseIdx + b0 + lane] = cum + x - h;      // exclusive
            cum += __shfl_sync(0xffffffffu, x, 31);
        }
        if (lane == 0) d_counts[g] = cum;
    }
    // ---- fused starts: last finishing block's warp 0 scans counts ----
    __shared__ int isLast;
    __syncthreads();
    if (threadIdx.x == 0) {
        __threadfence();
        isLast = (atomicAdd(&d_csDone, 1) == CSCAN_BLOCKS - 1);
    }
    __syncthreads();
    if (isLast && warpId == 0) {
        int cum = 0;
        #pragma unroll 1
        for (int b0 = 0; b0 <= NGROUP; b0 += 32) {
            const int idx = b0 + lane;
            // volatile: other SMs wrote counts; bypass potentially-stale L1
            const int v = (idx <= NGROUP) ? *(volatile int*)(d_counts + idx) : 0;
            int x = v;
            #pragma unroll
            for (int o = 1; o < 32; o <<= 1) {
                const int y = __shfl_up_sync(0xffffffffu, x, o);
                if (lane >= o) x += y;
            }
            if (idx <= NGROUP) d_starts[idx] = cum + x - v;   // exclusive
            cum += __shfl_sync(0xffffffffu, x, 31);
        }
        if (lane == 0) d_csDone = 0;          // reset for graph replay
    }
}

// ---------------- K3: stable scatter (full TLP: one item per thread) ------------
__global__ void __launch_bounds__(256)
scatter_kernel() {
    const int i = blockIdx.x * blockDim.x + threadIdx.x;
    if (i >= TOTAL) return;
    const int rg = d_rg[i];
    const int g = rg >> 16;
    const int b = i >> 9;                     // i / CHUNK
    const int pos = d_starts[g] + d_offT[g * NBLK + b] + (rg & 0xffff);
    d_osg[pos] = make_int2(i, g);
}

// ---------------- K4: main loss (R8 inner loop + block work-stealing) -----------
// Blocks acquire 8 warp-chunks at a time from a global counter: wave-1 blocks
// drain the queue (no wave-2 tail), wave-2 blocks exit immediately.
__global__ void __launch_bounds__(LOSS_THREADS)
loss_kernel(const float4* __restrict__ emb, float* __restrict__ out) {
    const int lane = threadIdx.x & 31;
    const int warpInBlock = threadIdx.x >> 5;
    const int valid_total = d_starts[NGROUP];

    __shared__ int sBase;
    float lsum = 0.0f, wsum = 0.0f;

    while (true) {
        if (threadIdx.x == 0) sBase = atomicAdd(&d_work, LOSS_THREADS / 32);
        __syncthreads();
        const int blockBase = sBase;
        __syncthreads();
        if (blockBase >= NWCHUNKS) break;
        const int lo = (blockBase + warpInBlock) * CHUNK_T;

        // ---- per-lane precompute (all 32 lanes) ----
        int anchor, negi, posi, isStart, validL;
        {
            const int t = lo + lane;
            const int2 og = __ldg(d_osg + t);
            anchor = og.x;
            const int g = og.y;
            const int st = d_starts[g];
            const int cnt = d_counts[g];
            const int np = neg_pos(t, st, cnt, valid_total);
            negi = __ldg(&d_osg[np].x);
            isStart = (t == st);
            const int pIdx = isStart ? (st + cnt - 1) : (t - 1);
            posi = __ldg(&d_osg[pIdx].x);
            validL = (g < NGROUP) && (cnt >= 2) && ((valid_total - cnt) > 0);
        }

        float4 aPrev = make_float4(0.f, 0.f, 0.f, 0.f);

        #pragma unroll 1
        for (int tp = 0; tp < CHUNK_T; tp += 4) {
            const unsigned FULL = 0xffffffffu;
            const int a0 = __shfl_sync(FULL, anchor, tp + 0);
            const int a1 = __shfl_sync(FULL, anchor, tp + 1);
            const int a2 = __shfl_sync(FULL, anchor, tp + 2);
            const int a3 = __shfl_sync(FULL, anchor, tp + 3);
            const int q0 = __shfl_sync(FULL, negi, tp + 0);
            const int q1 = __shfl_sync(FULL, negi, tp + 1);
            const int q2 = __shfl_sync(FULL, negi, tp + 2);
            const int q3 = __shfl_sync(FULL, negi, tp + 3);
            const int s0 = __shfl_sync(FULL, isStart, tp + 0);
            const int s1 = __shfl_sync(FULL, isStart, tp + 1);
            const int s2 = __shfl_sync(FULL, isStart, tp + 2);
            const int s3 = __shfl_sync(FULL, isStart, tp + 3);

            const float4 A0 = __ldg(&emb[a0 * 32 + lane]);
            const float4 A1 = __ldg(&emb[a1 * 32 + lane]);
            const float4 A2 = __ldg(&emb[a2 * 32 + lane]);
            const float4 A3 = __ldg(&emb[a3 * 32 + lane]);
            const float4 Q0 = __ldg(&emb[q0 * 32 + lane]);
            const float4 Q1 = __ldg(&emb[q1 * 32 + lane]);
            const float4 Q2 = __ldg(&emb[q2 * 32 + lane]);
            const float4 Q3 = __ldg(&emb[q3 * 32 + lane]);

            float4 P0;
            if (tp == 0 || s0) P0 = __ldg(&emb[__shfl_sync(FULL, posi, tp + 0) * 32 + lane]);
            else               P0 = aPrev;
            float4 P1 = s1 ? __ldg(&emb[__shfl_sync(FULL, posi, tp + 1) * 32 + lane]) : A0;
            float4 P2 = s2 ? __ldg(&emb[__shfl_sync(FULL, posi, tp + 2) * 32 + lane]) : A1;
            float4 P3 = s3 ? __ldg(&emb[__shfl_sync(FULL, posi, tp + 3) * 32 + lane]) : A2;
            aPrev = A3;

            float dp0 = A0.x*P0.x + A0.y*P0.y + A0.z*P0.z + A0.w*P0.w;
            float dn0 = A0.x*Q0.x + A0.y*Q0.y + A0.z*Q0.z + A0.w*Q0.w;
            float dp1 = A1.x*P1.x + A1.y*P1.y + A1.z*P1.z + A1.w*P1.w;
            float dn1 = A1.x*Q1.x + A1.y*Q1.y + A1.z*Q1.z + A1.w*Q1.w;
            float dp2 = A2.x*P2.x + A2.y*P2.y + A2.z*P2.z + A2.w*P2.w;
            float dn2 = A2.x*Q2.x + A2.y*Q2.y + A2.z*Q2.z + A2.w*Q2.w;
            float dp3 = A3.x*P3.x + A3.y*P3.y + A3.z*P3.z + A3.w*P3.w;
            float dn3 = A3.x*Q3.x + A3.y*Q3.y + A3.z*Q3.z + A3.w*Q3.w;
            #pragma unroll
            for (int o = 16; o; o >>= 1) {
                dp0 += __shfl_xor_sync(FULL, dp0, o);
                dn0 += __shfl_xor_sync(FULL, dn0, o);
                dp1 += __shfl_xor_sync(FULL, dp1, o);
                dn1 += __shfl_xor_sync(FULL, dn1, o);
                dp2 += __shfl_xor_sync(FULL, dp2, o);
                dn2 += __shfl_xor_sync(FULL, dn2, o);
                dp3 += __shfl_xor_sync(FULL, dp3, o);
                dn3 += __shfl_xor_sync(FULL, dn3, o);
            }

            // lanes 0..3 finish their own t in parallel
            const int vv = __shfl_sync(FULL, validL, tp + (lane & 3));
            if (lane < 4 && vv) {
                float dd;
                if      (lane == 0) dd = dn0 - dp0;
                else if (lane == 1) dd = dn1 - dp1;
                else if (lane == 2) dd = dn2 - dp2;
                else                dd = dn3 - dp3;
                dd *= 10.0f;                         // / TEMPERATURE
                lsum += fmaxf(dd, 0.0f) + log1pf(expf(-fabsf(dd)));
                wsum += 1.0f;
            }
        }
    }

    // warp-reduce the lane-distributed sums
    #pragma unroll
    for (int o = 16; o; o >>= 1) {
        lsum += __shfl_xor_sync(0xffffffffu, lsum, o);
        wsum += __shfl_xor_sync(0xffffffffu, wsum, o);
    }

    // deterministic block reduction
    __shared__ float sl[LOSS_THREADS / 32];
    __shared__ float sw[LOSS_THREADS / 32];
    __shared__ int isLast;
    if (lane == 0) { sl[warpInBlock] = lsum; sw[warpInBlock] = wsum; }
    __syncthreads();
    if (threadIdx.x == 0) {
        float L = 0.0f, W = 0.0f;
        #pragma unroll
        for (int i = 0; i < LOSS_THREADS / 32; i++) { L += sl[i]; W += sw[i]; }
        d_partials[2 * blockIdx.x]     = L;
        d_partials[2 * blockIdx.x + 1] = W;
        __threadfence();
        isLast = (atomicAdd(&d_done, 1) == LOSS_BLOCKS - 1);
    }
    __syncthreads();

    // last finishing block does the final reduction + counter resets
    if (isLast) {
        __shared__ float fl[256];
        __shared__ float fw[256];
        float L = 0.0f, W = 0.0f;
        for (int i = threadIdx.x; i < LOSS_BLOCKS; i += 256) {
            L += *(volatile float*)(d_partials + 2 * i);
            W += *(volatile float*)(d_partials + 2 * i + 1);
        }
        fl[threadIdx.x] = L; fw[threadIdx.x] = W;
        __syncthreads();
        for (int s = 128; s > 0; s >>= 1) {
            if (threadIdx.x < s) {
                fl[threadIdx.x] += fl[threadIdx.x + s];
                fw[threadIdx.x] += fw[threadIdx.x + s];
            }
            __syncthreads();
        }
        if (threadIdx.x == 0) {
            out[0] = fl[0] / fmaxf(fw[0], 1.0f);
            d_done = 0;                       // reset for graph replay
            d_work = 0;                       // reset work-stealing counter
        }
    }
}

// ---------------- launch ----------------
extern "C" void kernel_launch(void* const* d_in, const int* in_sizes, int n_in,
                              void* d_out, int out_size) {
    const float4* emb   = (const float4*)d_in[0];
    const int*    grp   = (const int*)d_in[1];
    const int*    mask  = (const int*)d_in[2];
    float*        out   = (float*)d_out;
    (void)in_sizes; (void)n_in; (void)out_size;

    rank_kernel<<<NBLK / RANK_WARPS, RANK_WARPS * 32>>>(grp, mask);
    colscan_kernel<<<CSCAN_BLOCKS, 256>>>();
    scatter_kernel<<<TOTAL / 256, 256>>>();
    loss_kernel<<<LOSS_BLOCKS, LOSS_THREADS>>>(emb, out);
}

// round 13
// speedup vs baseline: 1.3911x; 1.1219x over previous
#include <cuda_runtime.h>
#include <cuda_bf16.h>
#include <stdint.h>

// Problem constants (match reference setup_inputs)
#define TOTAL   262144        // B*N = 16*16384
#define NGROUP  1024          // NUM_GROUPS
#define GSENT   1024          // sentinel group for masked-out nodes
#define NBLK    512           // number of stable-sort chunks
#define CHUNK   512           // TOTAL / NBLK
#define RANK_THREADS 256      // 8 warps; one block per chunk
#define SUBCHUNK     64       // CHUNK / 8 elements per warp
#define LOSS_THREADS 256
#define LOSS_BLOCKS  1024     // 8192 warps
#define CHUNK_T      32       // sorted positions per warp
#define CSCAN_BLOCKS ((NGROUP + 1 + 7) / 8)   // 129 blocks of 8 warps

// ---------------- scratch (static __device__, no allocation) ----------------
__device__ int   d_rg[TOTAL];                    // packed (g<<16)|rank
__device__ int   d_histT[(NGROUP + 1) * NBLK];   // [g][b]
__device__ int   d_offT [(NGROUP + 1) * NBLK];   // [g][b] exclusive over b
__device__ int   d_counts[NGROUP + 1];
__device__ int   d_starts[NGROUP + 2];
__device__ int2  d_osg[TOTAL];                   // (orig index, group) per sorted pos
__device__ float d_partials[2 * LOSS_BLOCKS];
__device__ int   d_done;      // zero-init; last loss block resets to 0
__device__ int   d_csDone;    // zero-init; last colscan block resets to 0

// ---------------- threefry2x32 (JAX partitionable mode) ----------------
__device__ __forceinline__ unsigned rotl32(unsigned v, int d) {
    return (v << d) | (v >> (32 - d));
}

__device__ __forceinline__ void threefry2x32(unsigned k0, unsigned k1,
                                             unsigned& x0, unsigned& x1) {
    const unsigned ks0 = k0, ks1 = k1, ks2 = k0 ^ k1 ^ 0x1BD11BDAu;
    x0 += ks0; x1 += ks1;
#define TF_R4(a,b,c,d)                                  \
    x0 += x1; x1 = rotl32(x1, a); x1 ^= x0;             \
    x0 += x1; x1 = rotl32(x1, b); x1 ^= x0;             \
    x0 += x1; x1 = rotl32(x1, c); x1 ^= x0;             \
    x0 += x1; x1 = rotl32(x1, d); x1 ^= x0;
    TF_R4(13,15,26, 6); x0 += ks1; x1 += ks2 + 1u;
    TF_R4(17,29,16,24); x0 += ks2; x1 += ks0 + 2u;
    TF_R4(13,15,26, 6); x0 += ks0; x1 += ks1 + 3u;
    TF_R4(17,29,16,24); x0 += ks1; x1 += ks2 + 4u;
    TF_R4(13,15,26, 6); x0 += ks2; x1 += ks0 + 5u;
#undef TF_R4
}

// u[t]: counter = 64-bit flat index -> (hi=0, lo=t); draw = fold(out0^out1).
__device__ __forceinline__ float jax_uniform_at(int t) {
    unsigned x0 = 0u;
    unsigned x1 = (unsigned)t;
    threefry2x32(0u, 42u, x0, x1);       // jax.random.key(42) -> (0, 42)
    const unsigned bits = x0 ^ x1;
    return __uint_as_float((bits >> 9) | 0x3f800000u) - 1.0f;
}

// negative sorted-position for sorted index t
__device__ __forceinline__ int neg_pos(int t, int st, int cnt, int valid_total) {
    const float u = jax_uniform_at(t);
    const int comp = max(valid_total - cnt, 1);
    int r = (int)(u * (float)comp);
    if (r > comp - 1) r = comp - 1;
    int np_ = (r < st) ? r : r + cnt;
    if (np_ < 0) np_ = 0;
    if (np_ > TOTAL - 1) np_ = TOTAL - 1;
    return np_;
}

// ---------------- K1: block-parallel stable rank + per-chunk histogram ----------
// One 256-thread block per 512-element chunk. Each of 8 warps ranks its own
// 64-element sub-chunk (2 match rounds) into private bins; a per-group
// exclusive prefix across warp bins then converts local->chunk ranks.
// Ordering semantics identical to the serial 16-round version (stability kept).
__global__ void __launch_bounds__(RANK_THREADS)
rank_kernel(const int* __restrict__ groups, const int* __restrict__ mask) {
    __shared__ int bins[8][NGROUP + 1];      // [warp][group]
    const int warpId = threadIdx.x >> 5;
    const int lane = threadIdx.x & 31;
    const int b = blockIdx.x;                // chunk id 0..511
    // zero all warp bins
    for (int i = threadIdx.x; i < 8 * (NGROUP + 1); i += RANK_THREADS)
        ((int*)bins)[i] = 0;
    __syncthreads();

    // phase A: per-warp local rank within its 64-element sub-chunk
    const int base = b * CHUNK + warpId * SUBCHUNK;
    int gReg[2], rReg[2];
    #pragma unroll
    for (int k = 0; k < 2; k++) {
        const int i = base + k * 32 + lane;
        const int g = mask[i] ? groups[i] : GSENT;
        const unsigned m = __match_any_sync(0xffffffffu, g);
        const int rankInWarp = __popc(m & ((1u << lane) - 1u));
        const int leader = __ffs(m) - 1;
        int baseBin = 0;
        if (lane == leader) baseBin = atomicAdd(&bins[warpId][g], __popc(m));
        baseBin = __shfl_sync(0xffffffffu, baseBin, leader);
        gReg[k] = g;
        rReg[k] = baseBin + rankInWarp;
        __syncwarp();
    }
    __syncthreads();

    // phase B: per-group exclusive prefix across the 8 warp bins (in place)
    // smem addressing bins[w][g]: stride 1025 ints == 1 mod 32 -> conflict-free
    for (int g = threadIdx.x; g <= NGROUP; g += RANK_THREADS) {
        int c[8], s = 0;
        #pragma unroll
        for (int w = 0; w < 8; w++) { c[w] = bins[w][g]; }
        #pragma unroll
        for (int w = 0; w < 8; w++) { bins[w][g] = s; s += c[w]; }
        d_histT[g * NBLK + b] = s;
    }
    __syncthreads();

    // phase C: emit packed (g, chunk-rank)
    #pragma unroll
    for (int k = 0; k < 2; k++) {
        const int i = base + k * 32 + lane;
        const int g = gReg[k];
        d_rg[i] = (g << 16) | (bins[warpId][g] + rReg[k]);
    }
}

// ---------------- K2: per-group scan over chunks + fused starts scan ------------
__global__ void __launch_bounds__(256)
colscan_kernel() {
    const int warpId = threadIdx.x >> 5;
    const int lane = threadIdx.x & 31;
    const int g = blockIdx.x * 8 + warpId;
    if (g <= NGROUP) {
        const int baseIdx = g * NBLK;
        int cum = 0;
        #pragma unroll
        for (int b0 = 0; b0 < NBLK; b0 += 32) {
            const int h = d_histT[baseIdx + b0 + lane];     // coalesced 128B
            int x = h;
            #pragma unroll
            for (int o = 1; o < 32; o <<= 1) {
                const int y = __shfl_up_sync(0xffffffffu, x, o);
                if (lane >= o) x += y;
            }
            d_offT[baseIdx + b0 + lane] = cum + x - h;      // exclusive
            cum += __shfl_sync(0xffffffffu, x, 31);
        }
        if (lane == 0) d_counts[g] = cum;
    }
    // ---- fused starts: last finishing block's warp 0 scans counts ----
    __shared__ int isLast;
    __syncthreads();
    if (threadIdx.x == 0) {
        __threadfence();
        isLast = (atomicAdd(&d_csDone, 1) == CSCAN_BLOCKS - 1);
    }
    __syncthreads();
    if (isLast && warpId == 0) {
        int cum = 0;
        #pragma unroll 1
        for (int b0 = 0; b0 <= NGROUP; b0 += 32) {
            const int idx = b0 + lane;
            // volatile: other SMs wrote counts; bypass potentially-stale L1
            const int v = (idx <= NGROUP) ? *(volatile int*)(d_counts + idx) : 0;
            int x = v;
            #pragma unroll
            for (int o = 1; o < 32; o <<= 1) {
                const int y = __shfl_up_sync(0xffffffffu, x, o);
                if (lane >= o) x += y;
            }
            if (idx <= NGROUP) d_starts[idx] = cum + x - v;   // exclusive
            cum += __shfl_sync(0xffffffffu, x, 31);
        }
        if (lane == 0) d_csDone = 0;          // reset for graph replay
    }
}

// ---------------- K3: stable scatter (full TLP: one item per thread) ------------
__global__ void __launch_bounds__(256)
scatter_kernel() {
    const int i = blockIdx.x * blockDim.x + threadIdx.x;
    if (i >= TOTAL) return;
    const int rg = d_rg[i];
    const int g = rg >> 16;
    const int b = i >> 9;                     // i / CHUNK
    const int pos = d_starts[g] + d_offT[g * NBLK + b] + (rg & 0xffff);
    d_osg[pos] = make_int2(i, g);
}

// ---------------- K4: main loss (R8-proven version, verbatim) ----------------
__global__ void __launch_bounds__(LOSS_THREADS)
loss_kernel(const float4* __restrict__ emb, float* __restrict__ out) {
    const int lane = threadIdx.x & 31;
    const int warpInBlock = threadIdx.x >> 5;
    const int wid = blockIdx.x * (LOSS_THREADS / 32) + warpInBlock;
    const int lo = wid * CHUNK_T;
    const int valid_total = d_starts[NGROUP];

    // ---- per-lane precompute (all 32 lanes) ----
    int anchor, negi, posi, isStart, validL;
    {
        const int t = lo + lane;
        const int2 og = __ldg(d_osg + t);
        anchor = og.x;
        const int g = og.y;
        const int st = d_starts[g];
        const int cnt = d_counts[g];
        const int np = neg_pos(t, st, cnt, valid_total);
        negi = __ldg(&d_osg[np].x);
        isStart = (t == st);
        const int pIdx = isStart ? (st + cnt - 1) : (t - 1);
        posi = __ldg(&d_osg[pIdx].x);
        validL = (g < NGROUP) && (cnt >= 2) && ((valid_total - cnt) > 0);
    }

    float lsum = 0.0f, wsum = 0.0f;
    float4 aPrev = make_float4(0.f, 0.f, 0.f, 0.f);

    #pragma unroll 1
    for (int tp = 0; tp < CHUNK_T; tp += 4) {
        const unsigned FULL = 0xffffffffu;
        const int a0 = __shfl_sync(FULL, anchor, tp + 0);
        const int a1 = __shfl_sync(FULL, anchor, tp + 1);
        const int a2 = __shfl_sync(FULL, anchor, tp + 2);
        const int a3 = __shfl_sync(FULL, anchor, tp + 3);
        const int q0 = __shfl_sync(FULL, negi, tp + 0);
        const int q1 = __shfl_sync(FULL, negi, tp + 1);
        const int q2 = __shfl_sync(FULL, negi, tp + 2);
        const int q3 = __shfl_sync(FULL, negi, tp + 3);
        const int s0 = __shfl_sync(FULL, isStart, tp + 0);
        const int s1 = __shfl_sync(FULL, isStart, tp + 1);
        const int s2 = __shfl_sync(FULL, isStart, tp + 2);
        const int s3 = __shfl_sync(FULL, isStart, tp + 3);

        const float4 A0 = __ldg(&emb[a0 * 32 + lane]);
        const float4 A1 = __ldg(&emb[a1 * 32 + lane]);
        const float4 A2 = __ldg(&emb[a2 * 32 + lane]);
        const float4 A3 = __ldg(&emb[a3 * 32 + lane]);
        const float4 Q0 = __ldg(&emb[q0 * 32 + lane]);
        const float4 Q1 = __ldg(&emb[q1 * 32 + lane]);
        const float4 Q2 = __ldg(&emb[q2 * 32 + lane]);
        const float4 Q3 = __ldg(&emb[q3 * 32 + lane]);

        float4 P0;
        if (tp == 0 || s0) P0 = __ldg(&emb[__shfl_sync(FULL, posi, tp + 0) * 32 + lane]);
        else               P0 = aPrev;
        float4 P1 = s1 ? __ldg(&emb[__shfl_sync(FULL, posi, tp + 1) * 32 + lane]) : A0;
        float4 P2 = s2 ? __ldg(&emb[__shfl_sync(FULL, posi, tp + 2) * 32 + lane]) : A1;
        float4 P3 = s3 ? __ldg(&emb[__shfl_sync(FULL, posi, tp + 3) * 32 + lane]) : A2;
        aPrev = A3;

        float dp0 = A0.x*P0.x + A0.y*P0.y + A0.z*P0.z + A0.w*P0.w;
        float dn0 = A0.x*Q0.x + A0.y*Q0.y + A0.z*Q0.z + A0.w*Q0.w;
        float dp1 = A1.x*P1.x + A1.y*P1.y + A1.z*P1.z + A1.w*P1.w;
        float dn1 = A1.x*Q1.x + A1.y*Q1.y + A1.z*Q1.z + A1.w*Q1.w;
        float dp2 = A2.x*P2.x + A2.y*P2.y + A2.z*P2.z + A2.w*P2.w;
        float dn2 = A2.x*Q2.x + A2.y*Q2.y + A2.z*Q2.z + A2.w*Q2.w;
        float dp3 = A3.x*P3.x + A3.y*P3.y + A3.z*P3.z + A3.w*P3.w;
        float dn3 = A3.x*Q3.x + A3.y*Q3.y + A3.z*Q3.z + A3.w*Q3.w;
        #pragma unroll
        for (int o = 16; o; o >>= 1) {
            dp0 += __shfl_xor_sync(FULL, dp0, o);
            dn0 += __shfl_xor_sync(FULL, dn0, o);
            dp1 += __shfl_xor_sync(FULL, dp1, o);
            dn1 += __shfl_xor_sync(FULL, dn1, o);
            dp2 += __shfl_xor_sync(FULL, dp2, o);
            dn2 += __shfl_xor_sync(FULL, dn2, o);
            dp3 += __shfl_xor_sync(FULL, dp3, o);
            dn3 += __shfl_xor_sync(FULL, dn3, o);
        }

        // lanes 0..3 finish their own t in parallel
        const int vv = __shfl_sync(FULL, validL, tp + (lane & 3));
        if (lane < 4 && vv) {
            float dd;
            if      (lane == 0) dd = dn0 - dp0;
            else if (lane == 1) dd = dn1 - dp1;
            else if (lane == 2) dd = dn2 - dp2;
            else                dd = dn3 - dp3;
            dd *= 10.0f;                         // / TEMPERATURE
            lsum += fmaxf(dd, 0.0f) + log1pf(expf(-fabsf(dd)));
            wsum += 1.0f;
        }
    }

    // warp-reduce the lane-distributed sums
    #pragma unroll
    for (int o = 16; o; o >>= 1) {
        lsum += __shfl_xor_sync(0xffffffffu, lsum, o);
        wsum += __shfl_xor_sync(0xffffffffu, wsum, o);
    }

    // deterministic block reduction
    __shared__ float sl[LOSS_THREADS / 32];
    __shared__ float sw[LOSS_THREADS / 32];
    __shared__ int isLast;
    if (lane == 0) { sl[warpInBlock] = lsum; sw[warpInBlock] = wsum; }
    __syncthreads();
    if (threadIdx.x == 0) {
        float L = 0.0f, W = 0.0f;
        #pragma unroll
        for (int i = 0; i < LOSS_THREADS / 32; i++) { L += sl[i]; W += sw[i]; }
        d_partials[2 * blockIdx.x]     = L;
        d_partials[2 * blockIdx.x + 1] = W;
        __threadfence();
        isLast = (atomicAdd(&d_done, 1) == LOSS_BLOCKS - 1);
    }
    __syncthreads();

    // last finishing block does the deterministic final reduction
    if (isLast) {
        __shared__ float fl[256];
        __shared__ float fw[256];
        float L = 0.0f, W = 0.0f;
        for (int i = threadIdx.x; i < LOSS_BLOCKS; i += 256) {
            L += *(volatile float*)(d_partials + 2 * i);
            W += *(volatile float*)(d_partials + 2 * i + 1);
        }
        fl[threadIdx.x] = L; fw[threadIdx.x] = W;
        __syncthreads();
        for (int s = 128; s > 0; s >>= 1) {
            if (threadIdx.x < s) {
                fl[threadIdx.x] += fl[threadIdx.x + s];
                fw[threadIdx.x] += fw[threadIdx.x + s];
            }
            __syncthreads();
        }
        if (threadIdx.x == 0) {
            out[0] = fl[0] / fmaxf(fw[0], 1.0f);
            d_done = 0;                       // reset for graph replay
        }
    }
}

// ---------------- launch ----------------
extern "C" void kernel_launch(void* const* d_in, const int* in_sizes, int n_in,
                              void* d_out, int out_size) {
    const float4* emb   = (const float4*)d_in[0];
    const int*    grp   = (const int*)d_in[1];
    const int*    mask  = (const int*)d_in[2];
    float*        out   = (float*)d_out;
    (void)in_sizes; (void)n_in; (void)out_size;

    rank_kernel<<<NBLK, RANK_THREADS>>>(grp, mask);
    colscan_kernel<<<CSCAN_BLOCKS, 256>>>();
    scatter_kernel<<<TOTAL / 256, 256>>>();
    loss_kernel<<<LOSS_BLOCKS, LOSS_THREADS>>>(emb, out);
}

// round 14
// speedup vs baseline: 1.4084x; 1.0124x over previous
#include <cuda_runtime.h>
#include <cuda_bf16.h>
#include <stdint.h>

// Problem constants (match reference setup_inputs)
#define TOTAL   262144        // B*N = 16*16384
#define NGROUP  1024          // NUM_GROUPS
#define GSENT   1024          // sentinel group for masked-out nodes
#define NBLK    512           // number of stable-sort chunks
#define CHUNK   512           // TOTAL / NBLK
#define RANK_THREADS 256      // 8 warps; one block per chunk
#define SUBCHUNK     64       // CHUNK / 8 elements per warp
#define LOSS_THREADS 256
#define LOSS_BLOCKS  1024     // 8192 warps
#define CHUNK_T      32       // sorted positions per warp
#define CSCAN_BLOCKS ((NGROUP + 1 + 7) / 8)   // 129 blocks of 8 warps

// ---------------- scratch (static __device__, no allocation) ----------------
__device__ int   d_rg[TOTAL];                    // packed (g<<16)|rank
__device__ int   d_histT[(NGROUP + 1) * NBLK];   // [g][b]
__device__ int   d_offT [(NGROUP + 1) * NBLK];   // [g][b] exclusive over b
__device__ int   d_counts[NGROUP + 1];
__device__ int   d_starts[NGROUP + 2];
__device__ int2  d_osg[TOTAL];                   // (orig index, group) per sorted pos
__device__ float d_partials[2 * LOSS_BLOCKS];
__device__ int   d_done;      // zero-init; last loss block resets to 0
__device__ int   d_csDone;    // zero-init; last colscan block resets to 0

// ---------------- threefry2x32 (JAX partitionable mode) ----------------
__device__ __forceinline__ unsigned rotl32(unsigned v, int d) {
    return (v << d) | (v >> (32 - d));
}

__device__ __forceinline__ void threefry2x32(unsigned k0, unsigned k1,
                                             unsigned& x0, unsigned& x1) {
    const unsigned ks0 = k0, ks1 = k1, ks2 = k0 ^ k1 ^ 0x1BD11BDAu;
    x0 += ks0; x1 += ks1;
#define TF_R4(a,b,c,d)                                  \
    x0 += x1; x1 = rotl32(x1, a); x1 ^= x0;             \
    x0 += x1; x1 = rotl32(x1, b); x1 ^= x0;             \
    x0 += x1; x1 = rotl32(x1, c); x1 ^= x0;             \
    x0 += x1; x1 = rotl32(x1, d); x1 ^= x0;
    TF_R4(13,15,26, 6); x0 += ks1; x1 += ks2 + 1u;
    TF_R4(17,29,16,24); x0 += ks2; x1 += ks0 + 2u;
    TF_R4(13,15,26, 6); x0 += ks0; x1 += ks1 + 3u;
    TF_R4(17,29,16,24); x0 += ks1; x1 += ks2 + 4u;
    TF_R4(13,15,26, 6); x0 += ks2; x1 += ks0 + 5u;
#undef TF_R4
}

// u[t]: counter = 64-bit flat index -> (hi=0, lo=t); draw = fold(out0^out1).
__device__ __forceinline__ float jax_uniform_at(int t) {
    unsigned x0 = 0u;
    unsigned x1 = (unsigned)t;
    threefry2x32(0u, 42u, x0, x1);       // jax.random.key(42) -> (0, 42)
    const unsigned bits = x0 ^ x1;
    return __uint_as_float((bits >> 9) | 0x3f800000u) - 1.0f;
}

// negative sorted-position for sorted index t, given precomputed uniform u
__device__ __forceinline__ int neg_pos_u(float u, int st, int cnt, int valid_total) {
    const int comp = max(valid_total - cnt, 1);
    int r = (int)(u * (float)comp);
    if (r > comp - 1) r = comp - 1;
    int np_ = (r < st) ? r : r + cnt;
    if (np_ < 0) np_ = 0;
    if (np_ > TOTAL - 1) np_ = TOTAL - 1;
    return np_;
}

// ---------------- K1: block-parallel stable rank + per-chunk histogram ----------
__global__ void __launch_bounds__(RANK_THREADS)
rank_kernel(const int* __restrict__ groups, const int* __restrict__ mask) {
    __shared__ int bins[8][NGROUP + 1];      // [warp][group]
    const int warpId = threadIdx.x >> 5;
    const int lane = threadIdx.x & 31;
    const int b = blockIdx.x;                // chunk id 0..511
    for (int i = threadIdx.x; i < 8 * (NGROUP + 1); i += RANK_THREADS)
        ((int*)bins)[i] = 0;
    __syncthreads();

    // phase A: per-warp local rank within its 64-element sub-chunk
    const int base = b * CHUNK + warpId * SUBCHUNK;
    int gReg[2], rReg[2];
    #pragma unroll
    for (int k = 0; k < 2; k++) {
        const int i = base + k * 32 + lane;
        const int g = mask[i] ? groups[i] : GSENT;
        const unsigned m = __match_any_sync(0xffffffffu, g);
        const int rankInWarp = __popc(m & ((1u << lane) - 1u));
        const int leader = __ffs(m) - 1;
        int baseBin = 0;
        if (lane == leader) baseBin = atomicAdd(&bins[warpId][g], __popc(m));
        baseBin = __shfl_sync(0xffffffffu, baseBin, leader);
        gReg[k] = g;
        rReg[k] = baseBin + rankInWarp;
        __syncwarp();
    }
    __syncthreads();

    // phase B: per-group exclusive prefix across the 8 warp bins (in place)
    for (int g = threadIdx.x; g <= NGROUP; g += RANK_THREADS) {
        int c[8], s = 0;
        #pragma unroll
        for (int w = 0; w < 8; w++) { c[w] = bins[w][g]; }
        #pragma unroll
        for (int w = 0; w < 8; w++) { bins[w][g] = s; s += c[w]; }
        d_histT[g * NBLK + b] = s;
    }
    __syncthreads();

    // phase C: emit packed (g, chunk-rank)
    #pragma unroll
    for (int k = 0; k < 2; k++) {
        const int i = base + k * 32 + lane;
        const int g = gReg[k];
        d_rg[i] = (g << 16) | (bins[warpId][g] + rReg[k]);
    }
}

// ---------------- K2: per-group scan over chunks + fused starts scan ------------
__global__ void __launch_bounds__(256)
colscan_kernel() {
    const int warpId = threadIdx.x >> 5;
    const int lane = threadIdx.x & 31;
    const int g = blockIdx.x * 8 + warpId;
    cudaGridDependencySynchronize();         // PDL: wait for rank's histT
    if (g <= NGROUP) {
        const int baseIdx = g * NBLK;
        int cum = 0;
        #pragma unroll
        for (int b0 = 0; b0 < NBLK; b0 += 32) {
            const int h = d_histT[baseIdx + b0 + lane];     // coalesced 128B
            int x = h;
            #pragma unroll
            for (int o = 1; o < 32; o <<= 1) {
                const int y = __shfl_up_sync(0xffffffffu, x, o);
                if (lane >= o) x += y;
            }
            d_offT[baseIdx + b0 + lane] = cum + x - h;      // exclusive
            cum += __shfl_sync(0xffffffffu, x, 31);
        }
        if (lane == 0) d_counts[g] = cum;
    }
    // ---- fused starts: last finishing block's warp 0 scans counts ----
    __shared__ int isLast;
    __syncthreads();
    if (threadIdx.x == 0) {
        __threadfence();
        isLast = (atomicAdd(&d_csDone, 1) == CSCAN_BLOCKS - 1);
    }
    __syncthreads();
    if (isLast && warpId == 0) {
        int cum = 0;
        #pragma unroll 1
        for (int b0 = 0; b0 <= NGROUP; b0 += 32) {
            const int idx = b0 + lane;
            const int v = (idx <= NGROUP) ? *(volatile int*)(d_counts + idx) : 0;
            int x = v;
            #pragma unroll
            for (int o = 1; o < 32; o <<= 1) {
                const int y = __shfl_up_sync(0xffffffffu, x, o);
                if (lane >= o) x += y;
            }
            if (idx <= NGROUP) d_starts[idx] = cum + x - v;   // exclusive
            cum += __shfl_sync(0xffffffffu, x, 31);
        }
        if (lane == 0) d_csDone = 0;          // reset for graph replay
    }
}

// ---------------- K3: stable scatter (full TLP: one item per thread) ------------
__global__ void __launch_bounds__(256)
scatter_kernel() {
    const int i = blockIdx.x * blockDim.x + threadIdx.x;
    cudaGridDependencySynchronize();         // PDL: wait for colscan (and rank)
    if (i >= TOTAL) return;
    const int rg = d_rg[i];
    const int g = rg >> 16;
    const int b = i >> 9;                     // i / CHUNK
    const int pos = d_starts[g] + d_offT[g * NBLK + b] + (rg & 0xffff);
    d_osg[pos] = make_int2(i, g);
}

// ---------------- K4: main loss (R8 inner loop; threefry hoisted pre-sync) ------
__global__ void __launch_bounds__(LOSS_THREADS)
loss_kernel(const float4* __restrict__ emb, float* __restrict__ out) {
    const int lane = threadIdx.x & 31;
    const int warpInBlock = threadIdx.x >> 5;
    const int wid = blockIdx.x * (LOSS_THREADS / 32) + warpInBlock;
    const int lo = wid * CHUNK_T;

    // RNG depends only on t: overlap with scatter via PDL early launch
    const float uPre = jax_uniform_at(lo + lane);
    cudaGridDependencySynchronize();         // PDL: wait for scatter's d_osg

    const int valid_total = d_starts[NGROUP];

    // ---- per-lane precompute (all 32 lanes) ----
    int anchor, negi, posi, isStart, validL;
    {
        const int t = lo + lane;
        const int2 og = __ldg(d_osg + t);
        anchor = og.x;
        const int g = og.y;
        const int st = d_starts[g];
        const int cnt = d_counts[g];
        const int np = neg_pos_u(uPre, st, cnt, valid_total);
        negi = __ldg(&d_osg[np].x);
        isStart = (t == st);
        const int pIdx = isStart ? (st + cnt - 1) : (t - 1);
        posi = __ldg(&d_osg[pIdx].x);
        validL = (g < NGROUP) && (cnt >= 2) && ((valid_total - cnt) > 0);
    }

    float lsum = 0.0f, wsum = 0.0f;
    float4 aPrev = make_float4(0.f, 0.f, 0.f, 0.f);

    #pragma unroll 1
    for (int tp = 0; tp < CHUNK_T; tp += 4) {
        const unsigned FULL = 0xffffffffu;
        const int a0 = __shfl_sync(FULL, anchor, tp + 0);
        const int a1 = __shfl_sync(FULL, anchor, tp + 1);
        const int a2 = __shfl_sync(FULL, anchor, tp + 2);
        const int a3 = __shfl_sync(FULL, anchor, tp + 3);
        const int q0 = __shfl_sync(FULL, negi, tp + 0);
        const int q1 = __shfl_sync(FULL, negi, tp + 1);
        const int q2 = __shfl_sync(FULL, negi, tp + 2);
        const int q3 = __shfl_sync(FULL, negi, tp + 3);
        const int s0 = __shfl_sync(FULL, isStart, tp + 0);
        const int s1 = __shfl_sync(FULL, isStart, tp + 1);
        const int s2 = __shfl_sync(FULL, isStart, tp + 2);
        const int s3 = __shfl_sync(FULL, isStart, tp + 3);

        const float4 A0 = __ldg(&emb[a0 * 32 + lane]);
        const float4 A1 = __ldg(&emb[a1 * 32 + lane]);
        const float4 A2 = __ldg(&emb[a2 * 32 + lane]);
        const float4 A3 = __ldg(&emb[a3 * 32 + lane]);
        const float4 Q0 = __ldg(&emb[q0 * 32 + lane]);
        const float4 Q1 = __ldg(&emb[q1 * 32 + lane]);
        const float4 Q2 = __ldg(&emb[q2 * 32 + lane]);
        const float4 Q3 = __ldg(&emb[q3 * 32 + lane]);

        float4 P0;
        if (tp == 0 || s0) P0 = __ldg(&emb[__shfl_sync(FULL, posi, tp + 0) * 32 + lane]);
        else               P0 = aPrev;
        float4 P1 = s1 ? __ldg(&emb[__shfl_sync(FULL, posi, tp + 1) * 32 + lane]) : A0;
        float4 P2 = s2 ? __ldg(&emb[__shfl_sync(FULL, posi, tp + 2) * 32 + lane]) : A1;
        float4 P3 = s3 ? __ldg(&emb[__shfl_sync(FULL, posi, tp + 3) * 32 + lane]) : A2;
        aPrev = A3;

        float dp0 = A0.x*P0.x + A0.y*P0.y + A0.z*P0.z + A0.w*P0.w;
        float dn0 = A0.x*Q0.x + A0.y*Q0.y + A0.z*Q0.z + A0.w*Q0.w;
        float dp1 = A1.x*P1.x + A1.y*P1.y + A1.z*P1.z + A1.w*P1.w;
        float dn1 = A1.x*Q1.x + A1.y*Q1.y + A1.z*Q1.z + A1.w*Q1.w;
        float dp2 = A2.x*P2.x + A2.y*P2.y + A2.z*P2.z + A2.w*P2.w;
        float dn2 = A2.x*Q2.x + A2.y*Q2.y + A2.z*Q2.z + A2.w*Q2.w;
        float dp3 = A3.x*P3.x + A3.y*P3.y + A3.z*P3.z + A3.w*P3.w;
        float dn3 = A3.x*Q3.x + A3.y*Q3.y + A3.z*Q3.z + A3.w*Q3.w;
        #pragma unroll
        for (int o = 16; o; o >>= 1) {
            dp0 += __shfl_xor_sync(FULL, dp0, o);
            dn0 += __shfl_xor_sync(FULL, dn0, o);
            dp1 += __shfl_xor_sync(FULL, dp1, o);
            dn1 += __shfl_xor_sync(FULL, dn1, o);
            dp2 += __shfl_xor_sync(FULL, dp2, o);
            dn2 += __shfl_xor_sync(FULL, dn2, o);
            dp3 += __shfl_xor_sync(FULL, dp3, o);
            dn3 += __shfl_xor_sync(FULL, dn3, o);
        }

        // lanes 0..3 finish their own t in parallel
        const int vv = __shfl_sync(FULL, validL, tp + (lane & 3));
        if (lane < 4 && vv) {
            float dd;
            if      (lane == 0) dd = dn0 - dp0;
            else if (lane == 1) dd = dn1 - dp1;
            else if (lane == 2) dd = dn2 - dp2;
            else                dd = dn3 - dp3;
            dd *= 10.0f;                         // / TEMPERATURE
            lsum += fmaxf(dd, 0.0f) + log1pf(expf(-fabsf(dd)));
            wsum += 1.0f;
        }
    }

    // warp-reduce the lane-distributed sums
    #pragma unroll
    for (int o = 16; o; o >>= 1) {
        lsum += __shfl_xor_sync(0xffffffffu, lsum, o);
        wsum += __shfl_xor_sync(0xffffffffu, wsum, o);
    }

    // deterministic block reduction
    __shared__ float sl[LOSS_THREADS / 32];
    __shared__ float sw[LOSS_THREADS / 32];
    __shared__ int isLast;
    if (lane == 0) { sl[warpInBlock] = lsum; sw[warpInBlock] = wsum; }
    __syncthreads();
    if (threadIdx.x == 0) {
        float L = 0.0f, W = 0.0f;
        #pragma unroll
        for (int i = 0; i < LOSS_THREADS / 32; i++) { L += sl[i]; W += sw[i]; }
        d_partials[2 * blockIdx.x]     = L;
        d_partials[2 * blockIdx.x + 1] = W;
        __threadfence();
        isLast = (atomicAdd(&d_done, 1) == LOSS_BLOCKS - 1);
    }
    __syncthreads();

    // last finishing block does the deterministic final reduction
    if (isLast) {
        __shared__ float fl[256];
        __shared__ float fw[256];
        float L = 0.0f, W = 0.0f;
        for (int i = threadIdx.x; i < LOSS_BLOCKS; i += 256) {
            L += *(volatile float*)(d_partials + 2 * i);
            W += *(volatile float*)(d_partials + 2 * i + 1);
        }
        fl[threadIdx.x] = L; fw[threadIdx.x] = W;
        __syncthreads();
        for (int s = 128; s > 0; s >>= 1) {
            if (threadIdx.x < s) {
                fl[threadIdx.x] += fl[threadIdx.x + s];
                fw[threadIdx.x] += fw[threadIdx.x + s];
            }
            __syncthreads();
        }
        if (threadIdx.x == 0) {
            out[0] = fl[0] / fmaxf(fw[0], 1.0f);
            d_done = 0;                       // reset for graph replay
        }
    }
}

// ---------------- launch (PDL: overlap dependent-kernel launch with producer) ----
static inline void launch_pdl(void (*kern)(), dim3 grid, dim3 block) {
    cudaLaunchConfig_t cfg = {};
    cfg.gridDim = grid;
    cfg.blockDim = block;
    cudaLaunchAttribute attr[1];
    attr[0].id = cudaLaunchAttributeProgrammaticStreamSerialization;
    attr[0].val.programmaticStreamSerializationAllowed = 1;
    cfg.attrs = attr;
    cfg.numAttrs = 1;
    cudaLaunchKernelEx(&cfg, kern);
}

extern "C" void kernel_launch(void* const* d_in, const int* in_sizes, int n_in,
                              void* d_out, int out_size) {
    const float4* emb   = (const float4*)d_in[0];
    const int*    grp   = (const int*)d_in[1];
    const int*    mask  = (const int*)d_in[2];
    float*        out   = (float*)d_out;
    (void)in_sizes; (void)n_in; (void)out_size;

    rank_kernel<<<NBLK, RANK_THREADS>>>(grp, mask);
    launch_pdl(colscan_kernel, dim3(CSCAN_BLOCKS), dim3(256));
    launch_pdl(scatter_kernel, dim3(TOTAL / 256), dim3(256));
    {
        cudaLaunchConfig_t cfg = {};
        cfg.gridDim = dim3(LOSS_BLOCKS);
        cfg.blockDim = dim3(LOSS_THREADS);
        cudaLaunchAttribute attr[1];
        attr[0].id = cudaLaunchAttributeProgrammaticStreamSerialization;
        attr[0].val.programmaticStreamSerializationAllowed = 1;
        cfg.attrs = attr;
        cfg.numAttrs = 1;
        cudaLaunchKernelEx(&cfg, loss_kernel, emb, out);
    }
}